// round 14
// baseline (speedup 1.0000x reference)
#include <cuda_runtime.h>
#include <cuda_bf16.h>
#include <math.h>

#define BB 2
#define LQ 1024
#define CC 256
#define LK 4096
#define NCH 2
#define NHD 8
#define HD 32
#define EPSV 1e-8f
#define SPLITK 4

// ---------------- scratch (device globals; no allocation) ----------------
__device__ float g_partialm[BB * 16 * CC];
__device__ float g_sproj[BB * CC];
__device__ float g_V[BB * LK];
__device__ float g_pp[4 * BB * LK * 2];           // per-n-block P_hat partials
__device__ float g_attP[SPLITK * BB * LQ * CC];   // split-K partial O (fp32)
__device__ float g_lP[SPLITK * BB * NHD * LQ];    // split-K partial row sums
__device__ float g_Wcomb[CC * CC];                // Wo @ phi_W
__device__ float g_bcomb[CC];                     // bo @ phi_W + phi_b
__device__ __nv_bfloat16 g_hqb[BB * LQ * CC];
__device__ __nv_bfloat16 g_Qb[BB * LQ * CC];
__device__ __nv_bfloat16 g_fqT[BB * LK * CC];   // f_q transposed, bf16 [b][Lk][C]
__device__ __nv_bfloat16 g_qb[BB * LQ * CC];    // q (scaled) bf16
__device__ __nv_bfloat16 g_kb[BB * LK * CC];    // k bf16
__device__ __nv_bfloat16 g_vT[BB * CC * LK];    // v bf16 transposed [b][C][Lk]
__device__ __nv_bfloat16 g_attb[BB * LQ * CC];  // merged attention, bf16

__device__ __forceinline__ unsigned packbf(float x, float y) {
    __nv_bfloat162 h = __floats2bfloat162_rn(x, y);
    return *(unsigned*)&h;
}
__device__ __forceinline__ unsigned f2tf(float x) {
    unsigned r;
    asm("cvt.rna.tf32.f32 %0, %1;" : "=r"(r) : "f"(x));
    return r;
}

// ---------------- mean of S_SM over Lq (stage 1) ----------------
__global__ void mean_partial_kernel(const float* __restrict__ S_SM) {
    int b = blockIdx.y, seg = blockIdx.x, c = threadIdx.x;
    const float* base = S_SM + ((size_t)b * LQ + (size_t)seg * 64) * CC + c;
    float acc = 0.f;
    #pragma unroll 8
    for (int l = 0; l < 64; l++) acc += base[(size_t)l * CC];
    g_partialm[(b * 16 + seg) * CC + c] = acc;
}

// ---------------- fused: mean finalize + sproj (wide: grid BB x 8) ----------------
__global__ void meansproj_kernel(const float* __restrict__ qp_W1,
                                 const float* __restrict__ qp_b1) {
    __shared__ float smean[CC];
    int b = blockIdx.x, seg = blockIdx.y;
    int tid = threadIdx.x;
    {
        float acc = 0.f;
        #pragma unroll
        for (int s = 0; s < 16; s++) acc += g_partialm[(b * 16 + s) * CC + tid];
        smean[tid] = acc * (1.0f / LQ);
    }
    __syncthreads();
    int n = seg * 32 + (tid >> 3);     // 32 columns per block, 8 threads per column
    int cp = tid & 7;
    float acc = 0.f;
    for (int c = cp; c < CC; c += 8) acc += smean[c] * qp_W1[(size_t)c * CC + n];
    acc += __shfl_down_sync(0xffffffffu, acc, 4, 8);
    acc += __shfl_down_sync(0xffffffffu, acc, 2, 8);
    acc += __shfl_down_sync(0xffffffffu, acc, 1, 8);
    if (cp == 0) g_sproj[b * CC + n] = qp_b1[n] + acc;
}

// ---------------- Wcomb = Wo @ phi_W (fp32 tiled; runs concurrently on s3) ---------
__global__ __launch_bounds__(256)
void wcomb_gemm_kernel(const float* __restrict__ Wo, const float* __restrict__ phiW) {
    const int BM = 64, BN = 64, BK = 16;
    __shared__ __align__(16) float As[BK][BM];
    __shared__ __align__(16) float Bs[BK][BN];
    int m0 = blockIdx.x * BM, n0 = blockIdx.y * BN;
    int t = threadIdx.x;
    int tx = t % 16, ty = t / 16;
    float acc[4][4];
    #pragma unroll
    for (int i = 0; i < 4; i++)
        #pragma unroll
        for (int j = 0; j < 4; j++) acc[i][j] = 0.f;
    for (int k0 = 0; k0 < CC; k0 += BK) {
        {
            int mm = t / 4, kk4 = (t % 4) * 4;
            float4 av = *(const float4*)&Wo[(size_t)(m0 + mm) * CC + k0 + kk4];
            As[kk4 + 0][mm] = av.x; As[kk4 + 1][mm] = av.y;
            As[kk4 + 2][mm] = av.z; As[kk4 + 3][mm] = av.w;
        }
        {
            int kk = t / 16, nn4 = (t % 16) * 4;
            *(float4*)&Bs[kk][nn4] = *(const float4*)&phiW[(size_t)(k0 + kk) * CC + n0 + nn4];
        }
        __syncthreads();
        #pragma unroll
        for (int kk = 0; kk < BK; kk++) {
            float4 a4 = *(const float4*)&As[kk][ty * 4];
            float4 b4 = *(const float4*)&Bs[kk][tx * 4];
            float a[4] = {a4.x, a4.y, a4.z, a4.w};
            float b[4] = {b4.x, b4.y, b4.z, b4.w};
            #pragma unroll
            for (int i = 0; i < 4; i++)
                #pragma unroll
                for (int j = 0; j < 4; j++) acc[i][j] += a[i] * b[j];
        }
        __syncthreads();
    }
    #pragma unroll
    for (int i = 0; i < 4; i++)
        #pragma unroll
        for (int j = 0; j < 4; j++)
            g_Wcomb[(size_t)(m0 + ty * 4 + i) * CC + n0 + tx * 4 + j] = acc[i][j];
}

__global__ void bcomb_kernel(const float* __restrict__ phiW,
                             const float* __restrict__ bo,
                             const float* __restrict__ phi_b) {
    int n = threadIdx.x;
    float acc = phi_b[n];
    for (int c = 0; c < CC; c++) acc += bo[c] * phiW[(size_t)c * CC + n];
    g_bcomb[n] = acc;
}

// ---------------- f_q [b][C][Lk] fp32 -> fqT [b][Lk][C] bf16 ----------------
__global__ void transpose_fq_kernel(const float* __restrict__ f_q) {
    __shared__ float tile[32][33];
    int b = blockIdx.z;
    int l0 = blockIdx.x * 32, c0 = blockIdx.y * 32;
    int tx = threadIdx.x & 31, ty = threadIdx.x >> 5;  // 32 x 8
    const float* src = f_q + ((size_t)b * CC + c0) * LK + l0;
    #pragma unroll
    for (int j = 0; j < 4; j++) tile[ty + 8 * j][tx] = src[(size_t)(ty + 8 * j) * LK + tx];
    __syncthreads();
    unsigned* dst = (unsigned*)(g_fqT + ((size_t)b * LK + l0) * CC + c0);
    #pragma unroll
    for (int it = 0; it < 2; it++) {
        int i = threadIdx.x + it * 256;
        int r = i >> 4, p = i & 15;
        dst[(size_t)r * (CC / 2) + p] = packbf(tile[2 * p][r], tile[2 * p + 1][r]);
    }
}

// ---------------- tf32 GEMM for h + fused P_hat projection (double-buffered) -------
__global__ __launch_bounds__(128)
void gemm_tf32_hproj_kernel(const float* __restrict__ A, long strideA,
                            const float* __restrict__ W,
                            const float* __restrict__ bias,
                            const float* __restrict__ W2,
                            float* __restrict__ pp, int lda) {
    __shared__ unsigned As2[2][32][72];   // [buf][k][m]
    __shared__ unsigned Bs2[2][32][72];   // [buf][k][n]
    __shared__ float w2s[64][2];
    __shared__ float sred[2][2][64];      // [wn][ch][row]

    int bz = blockIdx.z;
    A += (size_t)bz * strideA;
    const float* biasP = bias + (size_t)bz * CC;
    int m0 = blockIdx.x * 64, n0 = blockIdx.y * 64;
    int tid = threadIdx.x, warp = tid >> 5, lane = tid & 31;
    int wm = warp & 1, wn = warp >> 1;
    int qr = lane >> 2, ql = lane & 3;

    if (tid < 64) {
        w2s[tid][0] = W2[(size_t)(n0 + tid) * 2 + 0];
        w2s[tid][1] = W2[(size_t)(n0 + tid) * 2 + 1];
    }

    // per-thread load coordinates (4 A-f4 + 4 B-f4 per tile)
    int akk[4], am4[4], bkk[4], bn4[4];
    #pragma unroll
    for (int it = 0; it < 4; it++) {
        int i = tid + it * 128;
        akk[it] = i >> 4; am4[it] = (i & 15) * 4;
        bkk[it] = i >> 4; bn4[it] = (i & 15) * 4;
    }

    float4 aR[4], bR[4];
    // prologue: tile 0 -> buf 0
    #pragma unroll
    for (int it = 0; it < 4; it++) {
        aR[it] = *(const float4*)&A[(size_t)akk[it] * lda + m0 + am4[it]];
        bR[it] = *(const float4*)&W[(size_t)bkk[it] * CC + n0 + bn4[it]];
    }
    #pragma unroll
    for (int it = 0; it < 4; it++) {
        As2[0][akk[it]][am4[it] + 0] = f2tf(aR[it].x);
        As2[0][akk[it]][am4[it] + 1] = f2tf(aR[it].y);
        As2[0][akk[it]][am4[it] + 2] = f2tf(aR[it].z);
        As2[0][akk[it]][am4[it] + 3] = f2tf(aR[it].w);
        Bs2[0][bkk[it]][bn4[it] + 0] = f2tf(bR[it].x);
        Bs2[0][bkk[it]][bn4[it] + 1] = f2tf(bR[it].y);
        Bs2[0][bkk[it]][bn4[it] + 2] = f2tf(bR[it].z);
        Bs2[0][bkk[it]][bn4[it] + 3] = f2tf(bR[it].w);
    }
    __syncthreads();

    float c[2][4][4];
    #pragma unroll
    for (int i = 0; i < 2; i++)
        #pragma unroll
        for (int j = 0; j < 4; j++)
            #pragma unroll
            for (int r = 0; r < 4; r++) c[i][j][r] = 0.f;

    const int NT = CC / 32;  // 8
    for (int t = 0; t < NT; t++) {
        int cur = t & 1;
        if (t + 1 < NT) {
            int k0 = (t + 1) * 32;
            #pragma unroll
            for (int it = 0; it < 4; it++) {
                aR[it] = *(const float4*)&A[(size_t)(k0 + akk[it]) * lda + m0 + am4[it]];
                bR[it] = *(const float4*)&W[(size_t)(k0 + bkk[it]) * CC + n0 + bn4[it]];
            }
        }
        #pragma unroll
        for (int kk = 0; kk < 32; kk += 8) {
            unsigned a[2][4], b[4][2];
            #pragma unroll
            for (int i = 0; i < 2; i++) {
                int r = wm * 32 + i * 16 + qr;
                a[i][0] = As2[cur][kk + ql][r];
                a[i][1] = As2[cur][kk + ql][r + 8];
                a[i][2] = As2[cur][kk + ql + 4][r];
                a[i][3] = As2[cur][kk + ql + 4][r + 8];
            }
            #pragma unroll
            for (int j = 0; j < 4; j++) {
                int n = wn * 32 + j * 8 + qr;
                b[j][0] = Bs2[cur][kk + ql][n];
                b[j][1] = Bs2[cur][kk + ql + 4][n];
            }
            #pragma unroll
            for (int i = 0; i < 2; i++)
                #pragma unroll
                for (int j = 0; j < 4; j++)
                    asm volatile(
                        "mma.sync.aligned.m16n8k8.row.col.f32.tf32.tf32.f32 "
                        "{%0,%1,%2,%3}, {%4,%5,%6,%7}, {%8,%9}, {%0,%1,%2,%3};\n"
                        : "+f"(c[i][j][0]), "+f"(c[i][j][1]), "+f"(c[i][j][2]), "+f"(c[i][j][3])
                        : "r"(a[i][0]), "r"(a[i][1]), "r"(a[i][2]), "r"(a[i][3]),
                          "r"(b[j][0]), "r"(b[j][1]));
        }
        if (t + 1 < NT) {
            int nxt = cur ^ 1;
            #pragma unroll
            for (int it = 0; it < 4; it++) {
                As2[nxt][akk[it]][am4[it] + 0] = f2tf(aR[it].x);
                As2[nxt][akk[it]][am4[it] + 1] = f2tf(aR[it].y);
                As2[nxt][akk[it]][am4[it] + 2] = f2tf(aR[it].z);
                As2[nxt][akk[it]][am4[it] + 3] = f2tf(aR[it].w);
                Bs2[nxt][bkk[it]][bn4[it] + 0] = f2tf(bR[it].x);
                Bs2[nxt][bkk[it]][bn4[it] + 1] = f2tf(bR[it].y);
                Bs2[nxt][bkk[it]][bn4[it] + 2] = f2tf(bR[it].z);
                Bs2[nxt][bkk[it]][bn4[it] + 3] = f2tf(bR[it].w);
            }
        }
        __syncthreads();
    }

    float p[2][4];
    #pragma unroll
    for (int ch = 0; ch < 2; ch++)
        #pragma unroll
        for (int s = 0; s < 4; s++) p[ch][s] = 0.f;
    #pragma unroll
    for (int i = 0; i < 2; i++) {
        #pragma unroll
        for (int j = 0; j < 4; j++) {
            int n = wn * 32 + j * 8 + 2 * ql;
            float b0 = biasP[n0 + n], b1 = biasP[n0 + n + 1];
            float h00 = fmaxf(c[i][j][0] + b0, 0.f);
            float h01 = fmaxf(c[i][j][1] + b1, 0.f);
            float h10 = fmaxf(c[i][j][2] + b0, 0.f);
            float h11 = fmaxf(c[i][j][3] + b1, 0.f);
            float wa0 = w2s[n][0], wb0 = w2s[n + 1][0];
            float wa1 = w2s[n][1], wb1 = w2s[n + 1][1];
            p[0][i * 2 + 0] += h00 * wa0 + h01 * wb0;
            p[1][i * 2 + 0] += h00 * wa1 + h01 * wb1;
            p[0][i * 2 + 1] += h10 * wa0 + h11 * wb0;
            p[1][i * 2 + 1] += h10 * wa1 + h11 * wb1;
        }
    }
    #pragma unroll
    for (int ch = 0; ch < 2; ch++)
        #pragma unroll
        for (int s = 0; s < 4; s++) {
            p[ch][s] += __shfl_xor_sync(0xffffffffu, p[ch][s], 1);
            p[ch][s] += __shfl_xor_sync(0xffffffffu, p[ch][s], 2);
        }
    if (ql == 0) {
        #pragma unroll
        for (int ch = 0; ch < 2; ch++)
            #pragma unroll
            for (int s = 0; s < 4; s++)
                sred[wn][ch][wm * 32 + s * 8 + qr] = p[ch][s];
    }
    __syncthreads();
    {
        int ch = tid >> 6, row = tid & 63;
        float v = sred[0][ch][row] + sred[1][ch][row];
        pp[(((size_t)blockIdx.y * BB + bz) * LK + m0 + row) * 2 + ch] = v;
    }
}

// ---------------- finalize P_hat + entropy + V ----------------
__device__ __forceinline__ float ent2(float x0, float x1) {
    float d = x0 - x1;
    float p0 = 1.f / (1.f + expf(-d));
    float p1 = 1.f / (1.f + expf(d));
    p0 = fmaxf(p0, EPSV);
    p1 = fmaxf(p1, EPSV);
    return -(p0 * logf(p0) + p1 * logf(p1));
}

__global__ void phat_final_kernel(const float* __restrict__ P,
                                  const float* __restrict__ qp_b2,
                                  float* __restrict__ out) {
    int idx = blockIdx.x * blockDim.x + threadIdx.x;
    if (idx >= BB * LK) return;
    int b = idx / LK, pix = idx % LK;
    float ph0 = qp_b2[0], ph1 = qp_b2[1];
    #pragma unroll
    for (int nb = 0; nb < 4; nb++) {
        float2 pv = *(const float2*)&g_pp[(((size_t)nb * BB + b) * LK + pix) * 2];
        ph0 += pv.x; ph1 += pv.y;
    }
    float* phat = out + (size_t)BB * LQ * CC;
    phat[((size_t)b * NCH + 0) * LK + pix] = ph0;
    phat[((size_t)b * NCH + 1) * LK + pix] = ph1;
    float p0 = P[((size_t)b * NCH + 0) * LK + pix];
    float p1 = P[((size_t)b * NCH + 1) * LK + pix];
    float Vv = ent2(ph0, ph1) - ent2(p0, p1);
    float* vout = out + (size_t)BB * LQ * CC + (size_t)BB * NCH * LK;
    vout[(size_t)b * LK + pix] = Vv;
    g_V[b * LK + pix] = Vv;
}

// ---------------- bf16 HMMA helpers ----------------
__device__ __forceinline__ void mma16816(float* c, const unsigned* a, const unsigned* b) {
    asm volatile(
        "mma.sync.aligned.m16n8k16.row.col.f32.bf16.bf16.f32 "
        "{%0,%1,%2,%3}, {%4,%5,%6,%7}, {%8,%9}, {%0,%1,%2,%3};\n"
        : "+f"(c[0]), "+f"(c[1]), "+f"(c[2]), "+f"(c[3])
        : "r"(a[0]), "r"(a[1]), "r"(a[2]), "r"(a[3]), "r"(b[0]), "r"(b[1]));
}

// ---------------- bf16 tensor-core GEMM ----------------
// EPI: 0 bias, 1 bias+relu, 2 Dsub - (acc+bias)
// OUTMODE: 0 fp32 row-major, 1 bf16 row-major (*outScale)
template <int EPI, int OUTMODE>
__global__ __launch_bounds__(128)
void hgemm_kernel(const __nv_bfloat16* __restrict__ A, long strideA,
                  const float* __restrict__ W, int ldw,
                  const float* __restrict__ bias, int biasStride,
                  const float* __restrict__ Dsub,
                  float* __restrict__ CoutF, __nv_bfloat16* __restrict__ CoutB,
                  long strideC, float outScale,
                  int M, int N, int K) {
    __shared__ __align__(16) __nv_bfloat16 As[64][40];
    __shared__ __align__(16) __nv_bfloat16 Bs[64][40];

    int bz = blockIdx.z;
    A += (size_t)bz * strideA;
    if (OUTMODE == 0) CoutF += (size_t)bz * strideC;
    else              CoutB += (size_t)bz * strideC;
    const float* biasP = bias + (size_t)bz * biasStride;

    int m0 = blockIdx.x * 64, n0 = blockIdx.y * 64;
    int tid = threadIdx.x, warp = tid >> 5, lane = tid & 31;
    int wm = warp & 1, wn = warp >> 1;
    int qrow = lane >> 2, qc2 = (lane & 3) * 2;

    float c[2][4][4];
    #pragma unroll
    for (int i = 0; i < 2; i++)
        #pragma unroll
        for (int j = 0; j < 4; j++)
            #pragma unroll
            for (int r = 0; r < 4; r++) c[i][j][r] = 0.f;

    for (int k0 = 0; k0 < K; k0 += 32) {
        #pragma unroll
        for (int it = 0; it < 2; it++) {
            int i = tid + it * 128;
            int row = i >> 2, seg = i & 3;
            *(uint4*)&As[row][seg * 8] =
                *(const uint4*)(A + (size_t)(m0 + row) * K + k0 + seg * 8);
        }
        #pragma unroll
        for (int it = 0; it < 4; it++) {
            int i = tid + it * 128;
            int kk = i >> 4, n4 = (i & 15) * 4;
            float4 wv = *(const float4*)(W + (size_t)(k0 + kk) * ldw + n0 + n4);
            Bs[n4 + 0][kk] = __float2bfloat16_rn(wv.x);
            Bs[n4 + 1][kk] = __float2bfloat16_rn(wv.y);
            Bs[n4 + 2][kk] = __float2bfloat16_rn(wv.z);
            Bs[n4 + 3][kk] = __float2bfloat16_rn(wv.w);
        }
        __syncthreads();
        #pragma unroll
        for (int kk = 0; kk < 32; kk += 16) {
            unsigned a[2][4], bfr[4][2];
            #pragma unroll
            for (int i = 0; i < 2; i++) {
                int r = wm * 32 + i * 16 + qrow;
                a[i][0] = *(const unsigned*)&As[r][kk + qc2];
                a[i][1] = *(const unsigned*)&As[r + 8][kk + qc2];
                a[i][2] = *(const unsigned*)&As[r][kk + qc2 + 8];
                a[i][3] = *(const unsigned*)&As[r + 8][kk + qc2 + 8];
            }
            #pragma unroll
            for (int j = 0; j < 4; j++) {
                int n = wn * 32 + j * 8 + qrow;
                bfr[j][0] = *(const unsigned*)&Bs[n][kk + qc2];
                bfr[j][1] = *(const unsigned*)&Bs[n][kk + qc2 + 8];
            }
            #pragma unroll
            for (int i = 0; i < 2; i++)
                #pragma unroll
                for (int j = 0; j < 4; j++) mma16816(c[i][j], a[i], bfr[j]);
        }
        __syncthreads();
    }

    #pragma unroll
    for (int i = 0; i < 2; i++) {
        #pragma unroll
        for (int j = 0; j < 4; j++) {
            int m = m0 + wm * 32 + i * 16 + qrow;
            int n = n0 + wn * 32 + j * 8 + qc2;
            float b0 = biasP[n], b1 = biasP[n + 1];
            float v0 = c[i][j][0] + b0, v1 = c[i][j][1] + b1;
            float v2 = c[i][j][2] + b0, v3 = c[i][j][3] + b1;
            if (EPI == 1) {
                v0 = fmaxf(v0, 0.f); v1 = fmaxf(v1, 0.f);
                v2 = fmaxf(v2, 0.f); v3 = fmaxf(v3, 0.f);
            }
            if (EPI == 2) {
                v0 = Dsub[(size_t)m * N + n] - v0;
                v1 = Dsub[(size_t)m * N + n + 1] - v1;
                v2 = Dsub[(size_t)(m + 8) * N + n] - v2;
                v3 = Dsub[(size_t)(m + 8) * N + n + 1] - v3;
            }
            if (OUTMODE == 0) {
                *(float2*)&CoutF[(size_t)m * N + n] = make_float2(v0, v1);
                *(float2*)&CoutF[(size_t)(m + 8) * N + n] = make_float2(v2, v3);
            } else {
                *(unsigned*)&CoutB[(size_t)m * N + n] = packbf(v0 * outScale, v1 * outScale);
                *(unsigned*)&CoutB[(size_t)(m + 8) * N + n] = packbf(v2 * outScale, v3 * outScale);
            }
        }
    }
}

// ---------------- fused k/v GEMM ----------------
__global__ __launch_bounds__(128)
void hgemm_kv_kernel(const __nv_bfloat16* __restrict__ A, long strideA,
                     const float* __restrict__ Wk, const float* __restrict__ Wv,
                     const float* __restrict__ bk, const float* __restrict__ bv,
                     __nv_bfloat16* __restrict__ Kout, long strideK,
                     __nv_bfloat16* __restrict__ Vout, long strideV,
                     int M, int N, int K) {
    __shared__ __align__(16) __nv_bfloat16 As[64][40];
    __shared__ __align__(16) __nv_bfloat16 Bsk[64][40];
    __shared__ __align__(16) __nv_bfloat16 Bsv[64][40];

    int bz = blockIdx.z;
    A += (size_t)bz * strideA;
    Kout += (size_t)bz * strideK;
    Vout += (size_t)bz * strideV;

    int m0 = blockIdx.x * 64, n0 = blockIdx.y * 64;
    int tid = threadIdx.x, warp = tid >> 5, lane = tid & 31;
    int wm = warp & 1, wn = warp >> 1;
    int qrow = lane >> 2, qc2 = (lane & 3) * 2;

    float ck[2][4][4], cv[2][4][4];
    #pragma unroll
    for (int i = 0; i < 2; i++)
        #pragma unroll
        for (int j = 0; j < 4; j++)
            #pragma unroll
            for (int r = 0; r < 4; r++) { ck[i][j][r] = 0.f; cv[i][j][r] = 0.f; }

    for (int k0 = 0; k0 < K; k0 += 32) {
        #pragma unroll
        for (int it = 0; it < 2; it++) {
            int i = tid + it * 128;
            int row = i >> 2, seg = i & 3;
            *(uint4*)&As[row][seg * 8] =
                *(const uint4*)(A + (size_t)(m0 + row) * K + k0 + seg * 8);
        }
        #pragma unroll
        for (int it = 0; it < 4; it++) {
            int i = tid + it * 128;
            int kk = i >> 4, n4 = (i & 15) * 4;
            float4 wv1 = *(const float4*)(Wk + (size_t)(k0 + kk) * N + n0 + n4);
            float4 wv2 = *(const float4*)(Wv + (size_t)(k0 + kk) * N + n0 + n4);
            Bsk[n4 + 0][kk] = __float2bfloat16_rn(wv1.x);
            Bsk[n4 + 1][kk] = __float2bfloat16_rn(wv1.y);
            Bsk[n4 + 2][kk] = __float2bfloat16_rn(wv1.z);
            Bsk[n4 + 3][kk] = __float2bfloat16_rn(wv1.w);
            Bsv[n4 + 0][kk] = __float2bfloat16_rn(wv2.x);
            Bsv[n4 + 1][kk] = __float2bfloat16_rn(wv2.y);
            Bsv[n4 + 2][kk] = __float2bfloat16_rn(wv2.z);
            Bsv[n4 + 3][kk] = __float2bfloat16_rn(wv2.w);
        }
        __syncthreads();
        #pragma unroll
        for (int kk = 0; kk < 32; kk += 16) {
            unsigned a[2][4], bk_f[4][2], bv_f[4][2];
            #pragma unroll
            for (int i = 0; i < 2; i++) {
                int r = wm * 32 + i * 16 + qrow;
                a[i][0] = *(const unsigned*)&As[r][kk + qc2];
                a[i][1] = *(const unsigned*)&As[r + 8][kk + qc2];
                a[i][2] = *(const unsigned*)&As[r][kk + qc2 + 8];
                a[i][3] = *(const unsigned*)&As[r + 8][kk + qc2 + 8];
            }
            #pragma unroll
            for (int j = 0; j < 4; j++) {
                int n = wn * 32 + j * 8 + qrow;
                bk_f[j][0] = *(const unsigned*)&Bsk[n][kk + qc2];
                bk_f[j][1] = *(const unsigned*)&Bsk[n][kk + qc2 + 8];
                bv_f[j][0] = *(const unsigned*)&Bsv[n][kk + qc2];
                bv_f[j][1] = *(const unsigned*)&Bsv[n][kk + qc2 + 8];
            }
            #pragma unroll
            for (int i = 0; i < 2; i++)
                #pragma unroll
                for (int j = 0; j < 4; j++) {
                    mma16816(ck[i][j], a[i], bk_f[j]);
                    mma16816(cv[i][j], a[i], bv_f[j]);
                }
        }
        __syncthreads();
    }

    #pragma unroll
    for (int i = 0; i < 2; i++) {
        #pragma unroll
        for (int j = 0; j < 4; j++) {
            int m = m0 + wm * 32 + i * 16 + qrow;
            int n = n0 + wn * 32 + j * 8 + qc2;
            float kb0 = bk[n], kb1 = bk[n + 1];
            float vb0 = bv[n], vb1 = bv[n + 1];
            *(unsigned*)&Kout[(size_t)m * N + n] = packbf(ck[i][j][0] + kb0, ck[i][j][1] + kb1);
            *(unsigned*)&Kout[(size_t)(m + 8) * N + n] = packbf(ck[i][j][2] + kb0, ck[i][j][3] + kb1);
            Vout[(size_t)n * M + m] = __float2bfloat16_rn(cv[i][j][0] + vb0);
            Vout[(size_t)(n + 1) * M + m] = __float2bfloat16_rn(cv[i][j][1] + vb1);
            Vout[(size_t)n * M + m + 8] = __float2bfloat16_rn(cv[i][j][2] + vb0);
            Vout[(size_t)(n + 1) * M + m + 8] = __float2bfloat16_rn(cv[i][j][3] + vb1);
        }
    }
}

// ---------------- bf16 HMMA GEMM with concatenated fp32 A = [A0 | A1] ----------------
__global__ __launch_bounds__(128)
void hgemm_cat_kernel(const float* __restrict__ A0, const float* __restrict__ A1,
                      const float* __restrict__ W,
                      const float* __restrict__ bias,
                      __nv_bfloat16* __restrict__ CoutB,
                      int M, int N, int K) {
    __shared__ __align__(16) __nv_bfloat16 As[64][40];
    __shared__ __align__(16) __nv_bfloat16 Bs[64][40];

    int m0 = blockIdx.x * 64, n0 = blockIdx.y * 64;
    int tid = threadIdx.x, warp = tid >> 5, lane = tid & 31;
    int wm = warp & 1, wn = warp >> 1;
    int qrow = lane >> 2, qc2 = (lane & 3) * 2;

    float c[2][4][4];
    #pragma unroll
    for (int i = 0; i < 2; i++)
        #pragma unroll
        for (int j = 0; j < 4; j++)
            #pragma unroll
            for (int r = 0; r < 4; r++) c[i][j][r] = 0.f;

    for (int k0 = 0; k0 < K; k0 += 32) {
        const float* Asrc = (k0 < CC) ? A0 : A1;
        int kloc = (k0 < CC) ? k0 : k0 - CC;
        #pragma unroll
        for (int it = 0; it < 4; it++) {
            int i = tid + it * 128;
            int row = i >> 3, seg = i & 7;
            float4 av = *(const float4*)&Asrc[(size_t)(m0 + row) * CC + kloc + seg * 4];
            As[row][seg * 4 + 0] = __float2bfloat16_rn(av.x);
            As[row][seg * 4 + 1] = __float2bfloat16_rn(av.y);
            As[row][seg * 4 + 2] = __float2bfloat16_rn(av.z);
            As[row][seg * 4 + 3] = __float2bfloat16_rn(av.w);
        }
        #pragma unroll
        for (int it = 0; it < 4; it++) {
            int i = tid + it * 128;
            int kk = i >> 4, n4 = (i & 15) * 4;
            float4 wv = *(const float4*)(W + (size_t)(k0 + kk) * N + n0 + n4);
            Bs[n4 + 0][kk] = __float2bfloat16_rn(wv.x);
            Bs[n4 + 1][kk] = __float2bfloat16_rn(wv.y);
            Bs[n4 + 2][kk] = __float2bfloat16_rn(wv.z);
            Bs[n4 + 3][kk] = __float2bfloat16_rn(wv.w);
        }
        __syncthreads();
        #pragma unroll
        for (int kk = 0; kk < 32; kk += 16) {
            unsigned a[2][4], bfr[4][2];
            #pragma unroll
            for (int i = 0; i < 2; i++) {
                int r = wm * 32 + i * 16 + qrow;
                a[i][0] = *(const unsigned*)&As[r][kk + qc2];
                a[i][1] = *(const unsigned*)&As[r + 8][kk + qc2];
                a[i][2] = *(const unsigned*)&As[r][kk + qc2 + 8];
                a[i][3] = *(const unsigned*)&As[r + 8][kk + qc2 + 8];
            }
            #pragma unroll
            for (int j = 0; j < 4; j++) {
                int n = wn * 32 + j * 8 + qrow;
                bfr[j][0] = *(const unsigned*)&Bs[n][kk + qc2];
                bfr[j][1] = *(const unsigned*)&Bs[n][kk + qc2 + 8];
            }
            #pragma unroll
            for (int i = 0; i < 2; i++)
                #pragma unroll
                for (int j = 0; j < 4; j++) mma16816(c[i][j], a[i], bfr[j]);
        }
        __syncthreads();
    }

    #pragma unroll
    for (int i = 0; i < 2; i++) {
        #pragma unroll
        for (int j = 0; j < 4; j++) {
            int m = m0 + wm * 32 + i * 16 + qrow;
            int n = n0 + wn * 32 + j * 8 + qc2;
            float b0 = bias[n], b1 = bias[n + 1];
            float v0 = fmaxf(c[i][j][0] + b0, 0.f), v1 = fmaxf(c[i][j][1] + b1, 0.f);
            float v2 = fmaxf(c[i][j][2] + b0, 0.f), v3 = fmaxf(c[i][j][3] + b1, 0.f);
            *(unsigned*)&CoutB[(size_t)m * N + n] = packbf(v0, v1);
            *(unsigned*)&CoutB[(size_t)(m + 8) * N + n] = packbf(v2, v3);
        }
    }
}

// ---------------- bf16 tensor-core attention (double-buffered, split-K x4) ----------------
__global__ __launch_bounds__(128)
void attn_mma_kernel(const __nv_bfloat16* __restrict__ qb,
                     const __nv_bfloat16* __restrict__ kb,
                     const __nv_bfloat16* __restrict__ vT) {
    __shared__ __align__(16) __nv_bfloat16 Ks[2][64][40];
    __shared__ __align__(16) __nv_bfloat16 Vt[2][32][72];
    __shared__ float bias_s[2][64];

    int qt = blockIdx.x, h = blockIdx.y;
    int b = blockIdx.z >> 2, quarter = blockIdx.z & 3;
    int tid = threadIdx.x, warp = tid >> 5, lane = tid & 31;
    int qr = qt * 64 + warp * 16 + (lane >> 2);
    int qc = (lane & 3) * 2;
    const int HK = LK / SPLITK;
    int kofs = quarter * HK;

    const __nv_bfloat16* kbase[4];
    const __nv_bfloat16* vbase[4];
    int krow[4], kcol[4], vrow[4], vcol[4];
    #pragma unroll
    for (int it = 0; it < 4; it++) {
        int i = tid + it * 128;
        krow[it] = i >> 3; kcol[it] = (i & 7) * 4;
        kbase[it] = kb + ((size_t)(b * LK) + kofs + krow[it]) * CC + h * HD + kcol[it];
        vrow[it] = i >> 4; vcol[it] = (i & 15) * 4;
        vbase[it] = vT + ((size_t)b * CC + h * HD + vrow[it]) * LK + kofs + vcol[it];
    }
    const float* vbias = g_V + b * LK + kofs + tid;

    unsigned aq[2][4];
    const __nv_bfloat16* qbase = qb + ((size_t)(b * LQ) + qr) * CC + h * HD;
    #pragma unroll
    for (int ks = 0; ks < 2; ks++) {
        aq[ks][0] = *(const unsigned*)(qbase + ks * 16 + qc);
        aq[ks][1] = *(const unsigned*)(qbase + (size_t)8 * CC + ks * 16 + qc);
        aq[ks][2] = *(const unsigned*)(qbase + ks * 16 + qc + 8);
        aq[ks][3] = *(const unsigned*)(qbase + (size_t)8 * CC + ks * 16 + qc + 8);
    }

    float o[4][4];
    #pragma unroll
    for (int i = 0; i < 4; i++)
        #pragma unroll
        for (int j = 0; j < 4; j++) o[i][j] = 0.f;
    float l0 = 0.f, l1 = 0.f;

    uint2 kreg[4], vreg[4];
    float breg = 0.f;
    #pragma unroll
    for (int it = 0; it < 4; it++) {
        kreg[it] = *(const uint2*)(kbase[it]);
        vreg[it] = *(const uint2*)(vbase[it]);
    }
    if (tid < 64) breg = vbias[0];
    #pragma unroll
    for (int it = 0; it < 4; it++) {
        *(uint2*)&Ks[0][krow[it]][kcol[it]] = kreg[it];
        *(uint2*)&Vt[0][vrow[it]][vcol[it]] = vreg[it];
    }
    if (tid < 64) bias_s[0][tid] = breg;
    __syncthreads();

    const int NT = HK / 64;
    for (int t = 0; t < NT; t++) {
        int cur = t & 1;
        if (t + 1 < NT) {
            int off = (t + 1) * 64;
            #pragma unroll
            for (int it = 0; it < 4; it++) {
                kreg[it] = *(const uint2*)(kbase[it] + (size_t)off * CC);
                vreg[it] = *(const uint2*)(vbase[it] + off);
            }
            if (tid < 64) breg = vbias[off];
        }

        float c[8][4];
        #pragma unroll
        for (int nt = 0; nt < 8; nt++) {
            c[nt][0] = c[nt][1] = c[nt][2] = c[nt][3] = 0.f;
            int n = nt * 8 + (lane >> 2);
            #pragma unroll
            for (int ks = 0; ks < 2; ks++) {
                unsigned bf[2];
                int k0 = ks * 16 + qc;
                bf[0] = *(const unsigned*)&Ks[cur][n][k0];
                bf[1] = *(const unsigned*)&Ks[cur][n][k0 + 8];
                mma16816(c[nt], aq[ks], bf);
            }
        }
        #pragma unroll
        for (int nt = 0; nt < 8; nt++) {
            float b0 = bias_s[cur][nt * 8 + qc], b1 = bias_s[cur][nt * 8 + qc + 1];
            c[nt][0] = __expf(c[nt][0] + b0);
            c[nt][1] = __expf(c[nt][1] + b1);
            c[nt][2] = __expf(c[nt][2] + b0);
            c[nt][3] = __expf(c[nt][3] + b1);
            l0 += c[nt][0] + c[nt][1];
            l1 += c[nt][2] + c[nt][3];
        }
        #pragma unroll
        for (int ks2 = 0; ks2 < 4; ks2++) {
            unsigned ap[4];
            ap[0] = packbf(c[2 * ks2][0], c[2 * ks2][1]);
            ap[1] = packbf(c[2 * ks2][2], c[2 * ks2][3]);
            ap[2] = packbf(c[2 * ks2 + 1][0], c[2 * ks2 + 1][1]);
            ap[3] = packbf(c[2 * ks2 + 1][2], c[2 * ks2 + 1][3]);
            #pragma unroll
            for (int nt2 = 0; nt2 < 4; nt2++) {
                int d = nt2 * 8 + (lane >> 2);
                int k0 = ks2 * 16 + qc;
                unsigned bf[2];
                bf[0] = *(const unsigned*)&Vt[cur][d][k0];
                bf[1] = *(const unsigned*)&Vt[cur][d][k0 + 8];
                mma16816(o[nt2], ap, bf);
            }
        }

        if (t + 1 < NT) {
            int nxt = cur ^ 1;
            #pragma unroll
            for (int it = 0; it < 4; it++) {
                *(uint2*)&Ks[nxt][krow[it]][kcol[it]] = kreg[it];
                *(uint2*)&Vt[nxt][vrow[it]][vcol[it]] = vreg[it];
            }
            if (tid < 64) bias_s[nxt][tid] = breg;
        }
        __syncthreads();
    }

    l0 += __shfl_xor_sync(0xffffffffu, l0, 1);
    l0 += __shfl_xor_sync(0xffffffffu, l0, 2);
    l1 += __shfl_xor_sync(0xffffffffu, l1, 1);
    l1 += __shfl_xor_sync(0xffffffffu, l1, 2);

    float* dstO = g_attP + (((size_t)quarter * BB + b) * LQ + qr) * CC + h * HD;
    #pragma unroll
    for (int nt2 = 0; nt2 < 4; nt2++) {
        int c0 = nt2 * 8 + qc;
        *(float2*)&dstO[c0] = make_float2(o[nt2][0], o[nt2][1]);
        *(float2*)&dstO[(size_t)8 * CC + c0] = make_float2(o[nt2][2], o[nt2][3]);
    }
    if ((lane & 3) == 0) {
        size_t lidx = (((size_t)quarter * BB + b) * NHD + h) * LQ;
        g_lP[lidx + qr] = l0;
        g_lP[lidx + qr + 8] = l1;
    }
}

// ---------------- split-K merge (reads partials ONCE) ----------------
__global__ void attn_merge_kernel(__nv_bfloat16* __restrict__ attout) {
    int p = blockIdx.x * blockDim.x + threadIdx.x;
    const int PPR = CC / 2;
    int row = p / PPR, c2 = (p % PPR) * 2;
    int b = row / LQ, q = row % LQ;
    int h = c2 >> 5;
    float l = 0.f;
    #pragma unroll
    for (int s = 0; s < SPLITK; s++)
        l += g_lP[(((size_t)s * BB + b) * NHD + h) * LQ + q];
    float inv = 1.f / l;
    size_t oi = (size_t)row * CC + c2;
    float ox = 0.f, oy = 0.f;
    #pragma unroll
    for (int s = 0; s < SPLITK; s++) {
        float2 a = *(float2*)&g_attP[(size_t)s * BB * LQ * CC + oi];
        ox += a.x; oy += a.y;
    }
    ((unsigned*)attout)[p] = packbf(ox * inv, oy * inv);
}

// ---------------- launch (multi-branch graph) ----------------
extern "C" void kernel_launch(void* const* d_in, const int* in_sizes, int n_in,
                              void* d_out, int out_size) {
    const float* S_QP   = (const float*)d_in[0];
    const float* S_SM   = (const float*)d_in[1];
    const float* f_q    = (const float*)d_in[2];
    const float* P      = (const float*)d_in[3];
    const float* qp_W1  = (const float*)d_in[4];
    const float* qp_b1  = (const float*)d_in[5];
    const float* qp_W2  = (const float*)d_in[6];
    const float* qp_b2  = (const float*)d_in[7];
    const float* phiQ_W1 = (const float*)d_in[8];
    const float* phiQ_b1 = (const float*)d_in[9];
    const float* phiQ_W2 = (const float*)d_in[10];
    const float* phiQ_b2 = (const float*)d_in[11];
    const float* Wq = (const float*)d_in[12];
    const float* bq = (const float*)d_in[13];
    const float* Wk = (const float*)d_in[14];
    const float* bk = (const float*)d_in[15];
    const float* Wv = (const float*)d_in[16];
    const float* bv = (const float*)d_in[17];
    const float* Wo = (const float*)d_in[18];
    const float* bo = (const float*)d_in[19];
    const float* phi_W = (const float*)d_in[20];
    const float* phi_b = (const float*)d_in[21];
    float* out = (float*)d_out;

    float *p_sproj, *p_pp, *p_Wcomb, *p_bcomb;
    __nv_bfloat16 *p_hqb, *p_Qb, *p_fqT, *p_qb, *p_kb, *p_vT, *p_attb;
    cudaGetSymbolAddress((void**)&p_sproj, g_sproj);
    cudaGetSymbolAddress((void**)&p_pp, g_pp);
    cudaGetSymbolAddress((void**)&p_Wcomb, g_Wcomb);
    cudaGetSymbolAddress((void**)&p_bcomb, g_bcomb);
    cudaGetSymbolAddress((void**)&p_hqb, g_hqb);
    cudaGetSymbolAddress((void**)&p_Qb, g_Qb);
    cudaGetSymbolAddress((void**)&p_fqT, g_fqT);
    cudaGetSymbolAddress((void**)&p_qb, g_qb);
    cudaGetSymbolAddress((void**)&p_kb, g_kb);
    cudaGetSymbolAddress((void**)&p_vT, g_vT);
    cudaGetSymbolAddress((void**)&p_attb, g_attb);

    const float attnScale = 0.17677669529663687f;  // 1/sqrt(32)

    static cudaStream_t s1 = nullptr, s2 = nullptr, s3 = nullptr;
    static cudaEvent_t evRoot = nullptr, ev1 = nullptr, ev2 = nullptr, ev3 = nullptr;
    if (!s1) {
        cudaStreamCreateWithFlags(&s1, cudaStreamNonBlocking);
        cudaStreamCreateWithFlags(&s2, cudaStreamNonBlocking);
        cudaStreamCreateWithFlags(&s3, cudaStreamNonBlocking);
        cudaEventCreateWithFlags(&evRoot, cudaEventDisableTiming);
        cudaEventCreateWithFlags(&ev1, cudaEventDisableTiming);
        cudaEventCreateWithFlags(&ev2, cudaEventDisableTiming);
        cudaEventCreateWithFlags(&ev3, cudaEventDisableTiming);
    }

    cudaEventRecord(evRoot, 0);
    cudaStreamWaitEvent(s1, evRoot, 0);
    cudaStreamWaitEvent(s2, evRoot, 0);
    cudaStreamWaitEvent(s3, evRoot, 0);

    // ---- branch A (main): mean -> sproj(wide) -> tf32 hproj(dbuf) -> P_hat/V ----
    mean_partial_kernel<<<dim3(16, BB), 256>>>(S_SM);
    meansproj_kernel<<<dim3(BB, 8), 256>>>(qp_W1, qp_b1);
    gemm_tf32_hproj_kernel<<<dim3(64, 4, BB), 128>>>(
        f_q, (long)CC * LK, qp_W1 + (size_t)CC * CC, p_sproj, qp_W2, p_pp, LK);
    phat_final_kernel<<<(BB * LK) / 256, 256>>>(P, qp_b2, out);

    // ---- branch B (s1): transpose -> fused k/v ----
    transpose_fq_kernel<<<dim3(LK / 32, CC / 32, BB), 256, 0, s1>>>(f_q);
    hgemm_kv_kernel<<<dim3(64, 4, BB), 128, 0, s1>>>(
        p_fqT, (long)LK * CC, Wk, Wv, bk, bv,
        p_kb, (long)LK * CC, p_vT, (long)CC * LK, 4096, 256, 256);

    // ---- branch C (s2): hq -> Q -> q ----
    hgemm_cat_kernel<<<dim3(32, 4, 1), 128, 0, s2>>>(
        S_QP, S_SM, phiQ_W1, phiQ_b1, p_hqb, 2048, 256, 512);
    hgemm_kernel<0, 1><<<dim3(32, 4, 1), 128, 0, s2>>>(
        p_hqb, 0, phiQ_W2, CC, phiQ_b2, 0, nullptr,
        nullptr, p_Qb, 0, 1.f, 2048, 256, 256);
    hgemm_kernel<0, 1><<<dim3(32, 4, 1), 128, 0, s2>>>(
        p_Qb, 0, Wq, CC, bq, 0, nullptr,
        nullptr, p_qb, 0, attnScale, 2048, 256, 256);

    // ---- branch D (s3): Wcomb = Wo@phi_W ; bcomb (hidden under prologue+attention) ----
    wcomb_gemm_kernel<<<dim3(4, 4), 256, 0, s3>>>(Wo, phi_W);
    bcomb_kernel<<<1, 256, 0, s3>>>(phi_W, bo, phi_b);

    // join compute branches for attention
    cudaEventRecord(ev1, s1);
    cudaEventRecord(ev2, s2);
    cudaStreamWaitEvent(0, ev1, 0);
    cudaStreamWaitEvent(0, ev2, 0);

    // ---- tail: attention -> merge (reads partials once) -> single fused GEMM ----
    attn_mma_kernel<<<dim3(LQ / 64, NHD, BB * SPLITK), 128>>>(p_qb, p_kb, p_vT);
    attn_merge_kernel<<<(BB * LQ * CC / 2) / 256, 256>>>(p_attb);
    cudaEventRecord(ev3, s3);
    cudaStreamWaitEvent(0, ev3, 0);
    // out = S_SM - (attb @ Wcomb + bcomb)
    hgemm_kernel<2, 0><<<dim3(32, 4, 1), 128>>>(
        p_attb, 0, p_Wcomb, CC, p_bcomb, 0, S_SM,
        out, nullptr, 0, 1.f, 2048, 256, 256);
}

// round 15
// speedup vs baseline: 1.2920x; 1.2920x over previous
#include <cuda_runtime.h>
#include <cuda_bf16.h>
#include <math.h>

#define BB 2
#define LQ 1024
#define CC 256
#define LK 4096
#define NCH 2
#define NHD 8
#define HD 32
#define EPSV 1e-8f
#define SPLITK 4

// ---------------- scratch (device globals; no allocation) ----------------
__device__ float g_partialm[BB * 16 * CC];
__device__ float g_sproj[BB * CC];
__device__ float g_V[BB * LK];
__device__ float g_pp[4 * BB * LK * 2];           // per-n-block P_hat partials
__device__ float g_attP[SPLITK * BB * LQ * CC];   // split-K partial O (fp32)
__device__ float g_lP[SPLITK * BB * NHD * LQ];    // split-K partial row sums
__device__ float g_Wcomb[CC * CC];                // Wo @ phi_W
__device__ float g_bcomb[CC];                     // bo @ phi_W + phi_b
__device__ __nv_bfloat16 g_hqb[BB * LQ * CC];
__device__ __nv_bfloat16 g_Qb[BB * LQ * CC];
__device__ __nv_bfloat16 g_fqT[BB * LK * CC];   // f_q transposed, bf16 [b][Lk][C]
__device__ __nv_bfloat16 g_qb[BB * LQ * CC];    // q (scaled) bf16
__device__ __nv_bfloat16 g_kb[BB * LK * CC];    // k bf16
__device__ __nv_bfloat16 g_vT[BB * CC * LK];    // v bf16 transposed [b][C][Lk]
__device__ __nv_bfloat16 g_attb[BB * LQ * CC];  // merged attention, bf16

__device__ __forceinline__ unsigned packbf(float x, float y) {
    __nv_bfloat162 h = __floats2bfloat162_rn(x, y);
    return *(unsigned*)&h;
}
__device__ __forceinline__ unsigned f2tf(float x) {
    unsigned r;
    asm("cvt.rna.tf32.f32 %0, %1;" : "=r"(r) : "f"(x));
    return r;
}

// ---------------- mean of S_SM over Lq (stage 1) ----------------
__global__ void mean_partial_kernel(const float* __restrict__ S_SM) {
    int b = blockIdx.y, seg = blockIdx.x, c = threadIdx.x;
    const float* base = S_SM + ((size_t)b * LQ + (size_t)seg * 64) * CC + c;
    float acc = 0.f;
    #pragma unroll 8
    for (int l = 0; l < 64; l++) acc += base[(size_t)l * CC];
    g_partialm[(b * 16 + seg) * CC + c] = acc;
}

// ---------------- fused: mean finalize + sproj (wide: grid BB x 8) ----------------
__global__ void meansproj_kernel(const float* __restrict__ qp_W1,
                                 const float* __restrict__ qp_b1) {
    __shared__ float smean[CC];
    int b = blockIdx.x, seg = blockIdx.y;
    int tid = threadIdx.x;
    {
        float acc = 0.f;
        #pragma unroll
        for (int s = 0; s < 16; s++) acc += g_partialm[(b * 16 + s) * CC + tid];
        smean[tid] = acc * (1.0f / LQ);
    }
    __syncthreads();
    int n = seg * 32 + (tid >> 3);     // 32 columns per block, 8 threads per column
    int cp = tid & 7;
    float acc = 0.f;
    for (int c = cp; c < CC; c += 8) acc += smean[c] * qp_W1[(size_t)c * CC + n];
    acc += __shfl_down_sync(0xffffffffu, acc, 4, 8);
    acc += __shfl_down_sync(0xffffffffu, acc, 2, 8);
    acc += __shfl_down_sync(0xffffffffu, acc, 1, 8);
    if (cp == 0) g_sproj[b * CC + n] = qp_b1[n] + acc;
}

// ---------------- Wcomb = Wo @ phi_W (fp32 tiled; runs concurrently on s3) ---------
__global__ __launch_bounds__(256)
void wcomb_gemm_kernel(const float* __restrict__ Wo, const float* __restrict__ phiW) {
    const int BM = 64, BN = 64, BK = 16;
    __shared__ __align__(16) float As[BK][BM];
    __shared__ __align__(16) float Bs[BK][BN];
    int m0 = blockIdx.x * BM, n0 = blockIdx.y * BN;
    int t = threadIdx.x;
    int tx = t % 16, ty = t / 16;
    float acc[4][4];
    #pragma unroll
    for (int i = 0; i < 4; i++)
        #pragma unroll
        for (int j = 0; j < 4; j++) acc[i][j] = 0.f;
    for (int k0 = 0; k0 < CC; k0 += BK) {
        {
            int mm = t / 4, kk4 = (t % 4) * 4;
            float4 av = *(const float4*)&Wo[(size_t)(m0 + mm) * CC + k0 + kk4];
            As[kk4 + 0][mm] = av.x; As[kk4 + 1][mm] = av.y;
            As[kk4 + 2][mm] = av.z; As[kk4 + 3][mm] = av.w;
        }
        {
            int kk = t / 16, nn4 = (t % 16) * 4;
            *(float4*)&Bs[kk][nn4] = *(const float4*)&phiW[(size_t)(k0 + kk) * CC + n0 + nn4];
        }
        __syncthreads();
        #pragma unroll
        for (int kk = 0; kk < BK; kk++) {
            float4 a4 = *(const float4*)&As[kk][ty * 4];
            float4 b4 = *(const float4*)&Bs[kk][tx * 4];
            float a[4] = {a4.x, a4.y, a4.z, a4.w};
            float b[4] = {b4.x, b4.y, b4.z, b4.w};
            #pragma unroll
            for (int i = 0; i < 4; i++)
                #pragma unroll
                for (int j = 0; j < 4; j++) acc[i][j] += a[i] * b[j];
        }
        __syncthreads();
    }
    #pragma unroll
    for (int i = 0; i < 4; i++)
        #pragma unroll
        for (int j = 0; j < 4; j++)
            g_Wcomb[(size_t)(m0 + ty * 4 + i) * CC + n0 + tx * 4 + j] = acc[i][j];
}

__global__ void bcomb_kernel(const float* __restrict__ phiW,
                             const float* __restrict__ bo,
                             const float* __restrict__ phi_b) {
    int n = threadIdx.x;
    float acc = phi_b[n];
    for (int c = 0; c < CC; c++) acc += bo[c] * phiW[(size_t)c * CC + n];
    g_bcomb[n] = acc;
}

// ---------------- f_q [b][C][Lk] fp32 -> fqT [b][Lk][C] bf16 ----------------
__global__ void transpose_fq_kernel(const float* __restrict__ f_q) {
    __shared__ float tile[32][33];
    int b = blockIdx.z;
    int l0 = blockIdx.x * 32, c0 = blockIdx.y * 32;
    int tx = threadIdx.x & 31, ty = threadIdx.x >> 5;  // 32 x 8
    const float* src = f_q + ((size_t)b * CC + c0) * LK + l0;
    #pragma unroll
    for (int j = 0; j < 4; j++) tile[ty + 8 * j][tx] = src[(size_t)(ty + 8 * j) * LK + tx];
    __syncthreads();
    unsigned* dst = (unsigned*)(g_fqT + ((size_t)b * LK + l0) * CC + c0);
    #pragma unroll
    for (int it = 0; it < 2; it++) {
        int i = threadIdx.x + it * 256;
        int r = i >> 4, p = i & 15;
        dst[(size_t)r * (CC / 2) + p] = packbf(tile[2 * p][r], tile[2 * p + 1][r]);
    }
}

// ---------------- tf32 tensor-core GEMM for h, with fused P_hat projection ----------
// (single-buffer: R10/R13 proven version)
__global__ __launch_bounds__(128)
void gemm_tf32_hproj_kernel(const float* __restrict__ A, long strideA,
                            const float* __restrict__ W,
                            const float* __restrict__ bias,
                            const float* __restrict__ W2,
                            float* __restrict__ pp, int lda) {
    __shared__ unsigned As2[32][72];   // [k][m]
    __shared__ unsigned Bs2[32][72];   // [k][n]
    __shared__ float w2s[64][2];
    __shared__ float sred[2][2][64];   // [wn][ch][row]

    int bz = blockIdx.z;
    A += (size_t)bz * strideA;
    const float* biasP = bias + (size_t)bz * CC;
    int m0 = blockIdx.x * 64, n0 = blockIdx.y * 64;
    int tid = threadIdx.x, warp = tid >> 5, lane = tid & 31;
    int wm = warp & 1, wn = warp >> 1;
    int qr = lane >> 2, ql = lane & 3;

    if (tid < 64) {
        w2s[tid][0] = W2[(size_t)(n0 + tid) * 2 + 0];
        w2s[tid][1] = W2[(size_t)(n0 + tid) * 2 + 1];
    }

    float c[2][4][4];
    #pragma unroll
    for (int i = 0; i < 2; i++)
        #pragma unroll
        for (int j = 0; j < 4; j++)
            #pragma unroll
            for (int r = 0; r < 4; r++) c[i][j][r] = 0.f;

    for (int k0 = 0; k0 < CC; k0 += 32) {
        #pragma unroll
        for (int it = 0; it < 4; it++) {
            int i = tid + it * 128;
            int kk = i >> 4, m4 = (i & 15) * 4;
            float4 av = *(const float4*)&A[(size_t)(k0 + kk) * lda + m0 + m4];
            As2[kk][m4 + 0] = f2tf(av.x);
            As2[kk][m4 + 1] = f2tf(av.y);
            As2[kk][m4 + 2] = f2tf(av.z);
            As2[kk][m4 + 3] = f2tf(av.w);
        }
        #pragma unroll
        for (int it = 0; it < 4; it++) {
            int i = tid + it * 128;
            int kk = i >> 4, n4 = (i & 15) * 4;
            float4 wv = *(const float4*)&W[(size_t)(k0 + kk) * CC + n0 + n4];
            Bs2[kk][n4 + 0] = f2tf(wv.x);
            Bs2[kk][n4 + 1] = f2tf(wv.y);
            Bs2[kk][n4 + 2] = f2tf(wv.z);
            Bs2[kk][n4 + 3] = f2tf(wv.w);
        }
        __syncthreads();
        #pragma unroll
        for (int kk = 0; kk < 32; kk += 8) {
            unsigned a[2][4], b[4][2];
            #pragma unroll
            for (int i = 0; i < 2; i++) {
                int r = wm * 32 + i * 16 + qr;
                a[i][0] = As2[kk + ql][r];
                a[i][1] = As2[kk + ql][r + 8];
                a[i][2] = As2[kk + ql + 4][r];
                a[i][3] = As2[kk + ql + 4][r + 8];
            }
            #pragma unroll
            for (int j = 0; j < 4; j++) {
                int n = wn * 32 + j * 8 + qr;
                b[j][0] = Bs2[kk + ql][n];
                b[j][1] = Bs2[kk + ql + 4][n];
            }
            #pragma unroll
            for (int i = 0; i < 2; i++)
                #pragma unroll
                for (int j = 0; j < 4; j++)
                    asm volatile(
                        "mma.sync.aligned.m16n8k8.row.col.f32.tf32.tf32.f32 "
                        "{%0,%1,%2,%3}, {%4,%5,%6,%7}, {%8,%9}, {%0,%1,%2,%3};\n"
                        : "+f"(c[i][j][0]), "+f"(c[i][j][1]), "+f"(c[i][j][2]), "+f"(c[i][j][3])
                        : "r"(a[i][0]), "r"(a[i][1]), "r"(a[i][2]), "r"(a[i][3]),
                          "r"(b[j][0]), "r"(b[j][1]));
        }
        __syncthreads();
    }

    float p[2][4];
    #pragma unroll
    for (int ch = 0; ch < 2; ch++)
        #pragma unroll
        for (int s = 0; s < 4; s++) p[ch][s] = 0.f;
    #pragma unroll
    for (int i = 0; i < 2; i++) {
        #pragma unroll
        for (int j = 0; j < 4; j++) {
            int n = wn * 32 + j * 8 + 2 * ql;
            float b0 = biasP[n0 + n], b1 = biasP[n0 + n + 1];
            float h00 = fmaxf(c[i][j][0] + b0, 0.f);
            float h01 = fmaxf(c[i][j][1] + b1, 0.f);
            float h10 = fmaxf(c[i][j][2] + b0, 0.f);
            float h11 = fmaxf(c[i][j][3] + b1, 0.f);
            float wa0 = w2s[n][0], wb0 = w2s[n + 1][0];
            float wa1 = w2s[n][1], wb1 = w2s[n + 1][1];
            p[0][i * 2 + 0] += h00 * wa0 + h01 * wb0;
            p[1][i * 2 + 0] += h00 * wa1 + h01 * wb1;
            p[0][i * 2 + 1] += h10 * wa0 + h11 * wb0;
            p[1][i * 2 + 1] += h10 * wa1 + h11 * wb1;
        }
    }
    #pragma unroll
    for (int ch = 0; ch < 2; ch++)
        #pragma unroll
        for (int s = 0; s < 4; s++) {
            p[ch][s] += __shfl_xor_sync(0xffffffffu, p[ch][s], 1);
            p[ch][s] += __shfl_xor_sync(0xffffffffu, p[ch][s], 2);
        }
    if (ql == 0) {
        #pragma unroll
        for (int ch = 0; ch < 2; ch++)
            #pragma unroll
            for (int s = 0; s < 4; s++)
                sred[wn][ch][wm * 32 + s * 8 + qr] = p[ch][s];
    }
    __syncthreads();
    {
        int ch = tid >> 6, row = tid & 63;
        float v = sred[0][ch][row] + sred[1][ch][row];
        pp[(((size_t)blockIdx.y * BB + bz) * LK + m0 + row) * 2 + ch] = v;
    }
}

// ---------------- finalize P_hat + entropy + V ----------------
__device__ __forceinline__ float ent2(float x0, float x1) {
    float d = x0 - x1;
    float p0 = 1.f / (1.f + expf(-d));
    float p1 = 1.f / (1.f + expf(d));
    p0 = fmaxf(p0, EPSV);
    p1 = fmaxf(p1, EPSV);
    return -(p0 * logf(p0) + p1 * logf(p1));
}

__global__ void phat_final_kernel(const float* __restrict__ P,
                                  const float* __restrict__ qp_b2,
                                  float* __restrict__ out) {
    int idx = blockIdx.x * blockDim.x + threadIdx.x;
    if (idx >= BB * LK) return;
    int b = idx / LK, pix = idx % LK;
    float ph0 = qp_b2[0], ph1 = qp_b2[1];
    #pragma unroll
    for (int nb = 0; nb < 4; nb++) {
        float2 pv = *(const float2*)&g_pp[(((size_t)nb * BB + b) * LK + pix) * 2];
        ph0 += pv.x; ph1 += pv.y;
    }
    float* phat = out + (size_t)BB * LQ * CC;
    phat[((size_t)b * NCH + 0) * LK + pix] = ph0;
    phat[((size_t)b * NCH + 1) * LK + pix] = ph1;
    float p0 = P[((size_t)b * NCH + 0) * LK + pix];
    float p1 = P[((size_t)b * NCH + 1) * LK + pix];
    float Vv = ent2(ph0, ph1) - ent2(p0, p1);
    float* vout = out + (size_t)BB * LQ * CC + (size_t)BB * NCH * LK;
    vout[(size_t)b * LK + pix] = Vv;
    g_V[b * LK + pix] = Vv;
}

// ---------------- bf16 HMMA helpers ----------------
__device__ __forceinline__ void mma16816(float* c, const unsigned* a, const unsigned* b) {
    asm volatile(
        "mma.sync.aligned.m16n8k16.row.col.f32.bf16.bf16.f32 "
        "{%0,%1,%2,%3}, {%4,%5,%6,%7}, {%8,%9}, {%0,%1,%2,%3};\n"
        : "+f"(c[0]), "+f"(c[1]), "+f"(c[2]), "+f"(c[3])
        : "r"(a[0]), "r"(a[1]), "r"(a[2]), "r"(a[3]), "r"(b[0]), "r"(b[1]));
}

// ---------------- bf16 tensor-core GEMM ----------------
// EPI: 0 bias, 1 bias+relu, 2 Dsub - (acc+bias)
// OUTMODE: 0 fp32 row-major, 1 bf16 row-major (*outScale)
template <int EPI, int OUTMODE>
__global__ __launch_bounds__(128)
void hgemm_kernel(const __nv_bfloat16* __restrict__ A, long strideA,
                  const float* __restrict__ W, int ldw,
                  const float* __restrict__ bias, int biasStride,
                  const float* __restrict__ Dsub,
                  float* __restrict__ CoutF, __nv_bfloat16* __restrict__ CoutB,
                  long strideC, float outScale,
                  int M, int N, int K) {
    __shared__ __align__(16) __nv_bfloat16 As[64][40];
    __shared__ __align__(16) __nv_bfloat16 Bs[64][40];

    int bz = blockIdx.z;
    A += (size_t)bz * strideA;
    if (OUTMODE == 0) CoutF += (size_t)bz * strideC;
    else              CoutB += (size_t)bz * strideC;
    const float* biasP = bias + (size_t)bz * biasStride;

    int m0 = blockIdx.x * 64, n0 = blockIdx.y * 64;
    int tid = threadIdx.x, warp = tid >> 5, lane = tid & 31;
    int wm = warp & 1, wn = warp >> 1;
    int qrow = lane >> 2, qc2 = (lane & 3) * 2;

    float c[2][4][4];
    #pragma unroll
    for (int i = 0; i < 2; i++)
        #pragma unroll
        for (int j = 0; j < 4; j++)
            #pragma unroll
            for (int r = 0; r < 4; r++) c[i][j][r] = 0.f;

    for (int k0 = 0; k0 < K; k0 += 32) {
        #pragma unroll
        for (int it = 0; it < 2; it++) {
            int i = tid + it * 128;
            int row = i >> 2, seg = i & 3;
            *(uint4*)&As[row][seg * 8] =
                *(const uint4*)(A + (size_t)(m0 + row) * K + k0 + seg * 8);
        }
        #pragma unroll
        for (int it = 0; it < 4; it++) {
            int i = tid + it * 128;
            int kk = i >> 4, n4 = (i & 15) * 4;
            float4 wv = *(const float4*)(W + (size_t)(k0 + kk) * ldw + n0 + n4);
            Bs[n4 + 0][kk] = __float2bfloat16_rn(wv.x);
            Bs[n4 + 1][kk] = __float2bfloat16_rn(wv.y);
            Bs[n4 + 2][kk] = __float2bfloat16_rn(wv.z);
            Bs[n4 + 3][kk] = __float2bfloat16_rn(wv.w);
        }
        __syncthreads();
        #pragma unroll
        for (int kk = 0; kk < 32; kk += 16) {
            unsigned a[2][4], bfr[4][2];
            #pragma unroll
            for (int i = 0; i < 2; i++) {
                int r = wm * 32 + i * 16 + qrow;
                a[i][0] = *(const unsigned*)&As[r][kk + qc2];
                a[i][1] = *(const unsigned*)&As[r + 8][kk + qc2];
                a[i][2] = *(const unsigned*)&As[r][kk + qc2 + 8];
                a[i][3] = *(const unsigned*)&As[r + 8][kk + qc2 + 8];
            }
            #pragma unroll
            for (int j = 0; j < 4; j++) {
                int n = wn * 32 + j * 8 + qrow;
                bfr[j][0] = *(const unsigned*)&Bs[n][kk + qc2];
                bfr[j][1] = *(const unsigned*)&Bs[n][kk + qc2 + 8];
            }
            #pragma unroll
            for (int i = 0; i < 2; i++)
                #pragma unroll
                for (int j = 0; j < 4; j++) mma16816(c[i][j], a[i], bfr[j]);
        }
        __syncthreads();
    }

    #pragma unroll
    for (int i = 0; i < 2; i++) {
        #pragma unroll
        for (int j = 0; j < 4; j++) {
            int m = m0 + wm * 32 + i * 16 + qrow;
            int n = n0 + wn * 32 + j * 8 + qc2;
            float b0 = biasP[n], b1 = biasP[n + 1];
            float v0 = c[i][j][0] + b0, v1 = c[i][j][1] + b1;
            float v2 = c[i][j][2] + b0, v3 = c[i][j][3] + b1;
            if (EPI == 1) {
                v0 = fmaxf(v0, 0.f); v1 = fmaxf(v1, 0.f);
                v2 = fmaxf(v2, 0.f); v3 = fmaxf(v3, 0.f);
            }
            if (EPI == 2) {
                v0 = Dsub[(size_t)m * N + n] - v0;
                v1 = Dsub[(size_t)m * N + n + 1] - v1;
                v2 = Dsub[(size_t)(m + 8) * N + n] - v2;
                v3 = Dsub[(size_t)(m + 8) * N + n + 1] - v3;
            }
            if (OUTMODE == 0) {
                *(float2*)&CoutF[(size_t)m * N + n] = make_float2(v0, v1);
                *(float2*)&CoutF[(size_t)(m + 8) * N + n] = make_float2(v2, v3);
            } else {
                *(unsigned*)&CoutB[(size_t)m * N + n] = packbf(v0 * outScale, v1 * outScale);
                *(unsigned*)&CoutB[(size_t)(m + 8) * N + n] = packbf(v2 * outScale, v3 * outScale);
            }
        }
    }
}

// ---------------- fused k/v GEMM ----------------
__global__ __launch_bounds__(128)
void hgemm_kv_kernel(const __nv_bfloat16* __restrict__ A, long strideA,
                     const float* __restrict__ Wk, const float* __restrict__ Wv,
                     const float* __restrict__ bk, const float* __restrict__ bv,
                     __nv_bfloat16* __restrict__ Kout, long strideK,
                     __nv_bfloat16* __restrict__ Vout, long strideV,
                     int M, int N, int K) {
    __shared__ __align__(16) __nv_bfloat16 As[64][40];
    __shared__ __align__(16) __nv_bfloat16 Bsk[64][40];
    __shared__ __align__(16) __nv_bfloat16 Bsv[64][40];

    int bz = blockIdx.z;
    A += (size_t)bz * strideA;
    Kout += (size_t)bz * strideK;
    Vout += (size_t)bz * strideV;

    int m0 = blockIdx.x * 64, n0 = blockIdx.y * 64;
    int tid = threadIdx.x, warp = tid >> 5, lane = tid & 31;
    int wm = warp & 1, wn = warp >> 1;
    int qrow = lane >> 2, qc2 = (lane & 3) * 2;

    float ck[2][4][4], cv[2][4][4];
    #pragma unroll
    for (int i = 0; i < 2; i++)
        #pragma unroll
        for (int j = 0; j < 4; j++)
            #pragma unroll
            for (int r = 0; r < 4; r++) { ck[i][j][r] = 0.f; cv[i][j][r] = 0.f; }

    for (int k0 = 0; k0 < K; k0 += 32) {
        #pragma unroll
        for (int it = 0; it < 2; it++) {
            int i = tid + it * 128;
            int row = i >> 2, seg = i & 3;
            *(uint4*)&As[row][seg * 8] =
                *(const uint4*)(A + (size_t)(m0 + row) * K + k0 + seg * 8);
        }
        #pragma unroll
        for (int it = 0; it < 4; it++) {
            int i = tid + it * 128;
            int kk = i >> 4, n4 = (i & 15) * 4;
            float4 wv1 = *(const float4*)(Wk + (size_t)(k0 + kk) * N + n0 + n4);
            float4 wv2 = *(const float4*)(Wv + (size_t)(k0 + kk) * N + n0 + n4);
            Bsk[n4 + 0][kk] = __float2bfloat16_rn(wv1.x);
            Bsk[n4 + 1][kk] = __float2bfloat16_rn(wv1.y);
            Bsk[n4 + 2][kk] = __float2bfloat16_rn(wv1.z);
            Bsk[n4 + 3][kk] = __float2bfloat16_rn(wv1.w);
            Bsv[n4 + 0][kk] = __float2bfloat16_rn(wv2.x);
            Bsv[n4 + 1][kk] = __float2bfloat16_rn(wv2.y);
            Bsv[n4 + 2][kk] = __float2bfloat16_rn(wv2.z);
            Bsv[n4 + 3][kk] = __float2bfloat16_rn(wv2.w);
        }
        __syncthreads();
        #pragma unroll
        for (int kk = 0; kk < 32; kk += 16) {
            unsigned a[2][4], bk_f[4][2], bv_f[4][2];
            #pragma unroll
            for (int i = 0; i < 2; i++) {
                int r = wm * 32 + i * 16 + qrow;
                a[i][0] = *(const unsigned*)&As[r][kk + qc2];
                a[i][1] = *(const unsigned*)&As[r + 8][kk + qc2];
                a[i][2] = *(const unsigned*)&As[r][kk + qc2 + 8];
                a[i][3] = *(const unsigned*)&As[r + 8][kk + qc2 + 8];
            }
            #pragma unroll
            for (int j = 0; j < 4; j++) {
                int n = wn * 32 + j * 8 + qrow;
                bk_f[j][0] = *(const unsigned*)&Bsk[n][kk + qc2];
                bk_f[j][1] = *(const unsigned*)&Bsk[n][kk + qc2 + 8];
                bv_f[j][0] = *(const unsigned*)&Bsv[n][kk + qc2];
                bv_f[j][1] = *(const unsigned*)&Bsv[n][kk + qc2 + 8];
            }
            #pragma unroll
            for (int i = 0; i < 2; i++)
                #pragma unroll
                for (int j = 0; j < 4; j++) {
                    mma16816(ck[i][j], a[i], bk_f[j]);
                    mma16816(cv[i][j], a[i], bv_f[j]);
                }
        }
        __syncthreads();
    }

    #pragma unroll
    for (int i = 0; i < 2; i++) {
        #pragma unroll
        for (int j = 0; j < 4; j++) {
            int m = m0 + wm * 32 + i * 16 + qrow;
            int n = n0 + wn * 32 + j * 8 + qc2;
            float kb0 = bk[n], kb1 = bk[n + 1];
            float vb0 = bv[n], vb1 = bv[n + 1];
            *(unsigned*)&Kout[(size_t)m * N + n] = packbf(ck[i][j][0] + kb0, ck[i][j][1] + kb1);
            *(unsigned*)&Kout[(size_t)(m + 8) * N + n] = packbf(ck[i][j][2] + kb0, ck[i][j][3] + kb1);
            Vout[(size_t)n * M + m] = __float2bfloat16_rn(cv[i][j][0] + vb0);
            Vout[(size_t)(n + 1) * M + m] = __float2bfloat16_rn(cv[i][j][1] + vb1);
            Vout[(size_t)n * M + m + 8] = __float2bfloat16_rn(cv[i][j][2] + vb0);
            Vout[(size_t)(n + 1) * M + m + 8] = __float2bfloat16_rn(cv[i][j][3] + vb1);
        }
    }
}

// ---------------- bf16 HMMA GEMM with concatenated fp32 A = [A0 | A1] ----------------
__global__ __launch_bounds__(128)
void hgemm_cat_kernel(const float* __restrict__ A0, const float* __restrict__ A1,
                      const float* __restrict__ W,
                      const float* __restrict__ bias,
                      __nv_bfloat16* __restrict__ CoutB,
                      int M, int N, int K) {
    __shared__ __align__(16) __nv_bfloat16 As[64][40];
    __shared__ __align__(16) __nv_bfloat16 Bs[64][40];

    int m0 = blockIdx.x * 64, n0 = blockIdx.y * 64;
    int tid = threadIdx.x, warp = tid >> 5, lane = tid & 31;
    int wm = warp & 1, wn = warp >> 1;
    int qrow = lane >> 2, qc2 = (lane & 3) * 2;

    float c[2][4][4];
    #pragma unroll
    for (int i = 0; i < 2; i++)
        #pragma unroll
        for (int j = 0; j < 4; j++)
            #pragma unroll
            for (int r = 0; r < 4; r++) c[i][j][r] = 0.f;

    for (int k0 = 0; k0 < K; k0 += 32) {
        const float* Asrc = (k0 < CC) ? A0 : A1;
        int kloc = (k0 < CC) ? k0 : k0 - CC;
        #pragma unroll
        for (int it = 0; it < 4; it++) {
            int i = tid + it * 128;
            int row = i >> 3, seg = i & 7;
            float4 av = *(const float4*)&Asrc[(size_t)(m0 + row) * CC + kloc + seg * 4];
            As[row][seg * 4 + 0] = __float2bfloat16_rn(av.x);
            As[row][seg * 4 + 1] = __float2bfloat16_rn(av.y);
            As[row][seg * 4 + 2] = __float2bfloat16_rn(av.z);
            As[row][seg * 4 + 3] = __float2bfloat16_rn(av.w);
        }
        #pragma unroll
        for (int it = 0; it < 4; it++) {
            int i = tid + it * 128;
            int kk = i >> 4, n4 = (i & 15) * 4;
            float4 wv = *(const float4*)(W + (size_t)(k0 + kk) * N + n0 + n4);
            Bs[n4 + 0][kk] = __float2bfloat16_rn(wv.x);
            Bs[n4 + 1][kk] = __float2bfloat16_rn(wv.y);
            Bs[n4 + 2][kk] = __float2bfloat16_rn(wv.z);
            Bs[n4 + 3][kk] = __float2bfloat16_rn(wv.w);
        }
        __syncthreads();
        #pragma unroll
        for (int kk = 0; kk < 32; kk += 16) {
            unsigned a[2][4], bfr[4][2];
            #pragma unroll
            for (int i = 0; i < 2; i++) {
                int r = wm * 32 + i * 16 + qrow;
                a[i][0] = *(const unsigned*)&As[r][kk + qc2];
                a[i][1] = *(const unsigned*)&As[r + 8][kk + qc2];
                a[i][2] = *(const unsigned*)&As[r][kk + qc2 + 8];
                a[i][3] = *(const unsigned*)&As[r + 8][kk + qc2 + 8];
            }
            #pragma unroll
            for (int j = 0; j < 4; j++) {
                int n = wn * 32 + j * 8 + qrow;
                bfr[j][0] = *(const unsigned*)&Bs[n][kk + qc2];
                bfr[j][1] = *(const unsigned*)&Bs[n][kk + qc2 + 8];
            }
            #pragma unroll
            for (int i = 0; i < 2; i++)
                #pragma unroll
                for (int j = 0; j < 4; j++) mma16816(c[i][j], a[i], bfr[j]);
        }
        __syncthreads();
    }

    #pragma unroll
    for (int i = 0; i < 2; i++) {
        #pragma unroll
        for (int j = 0; j < 4; j++) {
            int m = m0 + wm * 32 + i * 16 + qrow;
            int n = n0 + wn * 32 + j * 8 + qc2;
            float b0 = bias[n], b1 = bias[n + 1];
            float v0 = fmaxf(c[i][j][0] + b0, 0.f), v1 = fmaxf(c[i][j][1] + b1, 0.f);
            float v2 = fmaxf(c[i][j][2] + b0, 0.f), v3 = fmaxf(c[i][j][3] + b1, 0.f);
            *(unsigned*)&CoutB[(size_t)m * N + n] = packbf(v0, v1);
            *(unsigned*)&CoutB[(size_t)(m + 8) * N + n] = packbf(v2, v3);
        }
    }
}

// ---------------- bf16 tensor-core attention (double-buffered, split-K x4) ----------------
__global__ __launch_bounds__(128)
void attn_mma_kernel(const __nv_bfloat16* __restrict__ qb,
                     const __nv_bfloat16* __restrict__ kb,
                     const __nv_bfloat16* __restrict__ vT) {
    __shared__ __align__(16) __nv_bfloat16 Ks[2][64][40];
    __shared__ __align__(16) __nv_bfloat16 Vt[2][32][72];
    __shared__ float bias_s[2][64];

    int qt = blockIdx.x, h = blockIdx.y;
    int b = blockIdx.z >> 2, quarter = blockIdx.z & 3;
    int tid = threadIdx.x, warp = tid >> 5, lane = tid & 31;
    int qr = qt * 64 + warp * 16 + (lane >> 2);
    int qc = (lane & 3) * 2;
    const int HK = LK / SPLITK;
    int kofs = quarter * HK;

    const __nv_bfloat16* kbase[4];
    const __nv_bfloat16* vbase[4];
    int krow[4], kcol[4], vrow[4], vcol[4];
    #pragma unroll
    for (int it = 0; it < 4; it++) {
        int i = tid + it * 128;
        krow[it] = i >> 3; kcol[it] = (i & 7) * 4;
        kbase[it] = kb + ((size_t)(b * LK) + kofs + krow[it]) * CC + h * HD + kcol[it];
        vrow[it] = i >> 4; vcol[it] = (i & 15) * 4;
        vbase[it] = vT + ((size_t)b * CC + h * HD + vrow[it]) * LK + kofs + vcol[it];
    }
    const float* vbias = g_V + b * LK + kofs + tid;

    unsigned aq[2][4];
    const __nv_bfloat16* qbase = qb + ((size_t)(b * LQ) + qr) * CC + h * HD;
    #pragma unroll
    for (int ks = 0; ks < 2; ks++) {
        aq[ks][0] = *(const unsigned*)(qbase + ks * 16 + qc);
        aq[ks][1] = *(const unsigned*)(qbase + (size_t)8 * CC + ks * 16 + qc);
        aq[ks][2] = *(const unsigned*)(qbase + ks * 16 + qc + 8);
        aq[ks][3] = *(const unsigned*)(qbase + (size_t)8 * CC + ks * 16 + qc + 8);
    }

    float o[4][4];
    #pragma unroll
    for (int i = 0; i < 4; i++)
        #pragma unroll
        for (int j = 0; j < 4; j++) o[i][j] = 0.f;
    float l0 = 0.f, l1 = 0.f;

    uint2 kreg[4], vreg[4];
    float breg = 0.f;
    #pragma unroll
    for (int it = 0; it < 4; it++) {
        kreg[it] = *(const uint2*)(kbase[it]);
        vreg[it] = *(const uint2*)(vbase[it]);
    }
    if (tid < 64) breg = vbias[0];
    #pragma unroll
    for (int it = 0; it < 4; it++) {
        *(uint2*)&Ks[0][krow[it]][kcol[it]] = kreg[it];
        *(uint2*)&Vt[0][vrow[it]][vcol[it]] = vreg[it];
    }
    if (tid < 64) bias_s[0][tid] = breg;
    __syncthreads();

    const int NT = HK / 64;
    for (int t = 0; t < NT; t++) {
        int cur = t & 1;
        if (t + 1 < NT) {
            int off = (t + 1) * 64;
            #pragma unroll
            for (int it = 0; it < 4; it++) {
                kreg[it] = *(const uint2*)(kbase[it] + (size_t)off * CC);
                vreg[it] = *(const uint2*)(vbase[it] + off);
            }
            if (tid < 64) breg = vbias[off];
        }

        float c[8][4];
        #pragma unroll
        for (int nt = 0; nt < 8; nt++) {
            c[nt][0] = c[nt][1] = c[nt][2] = c[nt][3] = 0.f;
            int n = nt * 8 + (lane >> 2);
            #pragma unroll
            for (int ks = 0; ks < 2; ks++) {
                unsigned bf[2];
                int k0 = ks * 16 + qc;
                bf[0] = *(const unsigned*)&Ks[cur][n][k0];
                bf[1] = *(const unsigned*)&Ks[cur][n][k0 + 8];
                mma16816(c[nt], aq[ks], bf);
            }
        }
        #pragma unroll
        for (int nt = 0; nt < 8; nt++) {
            float b0 = bias_s[cur][nt * 8 + qc], b1 = bias_s[cur][nt * 8 + qc + 1];
            c[nt][0] = __expf(c[nt][0] + b0);
            c[nt][1] = __expf(c[nt][1] + b1);
            c[nt][2] = __expf(c[nt][2] + b0);
            c[nt][3] = __expf(c[nt][3] + b1);
            l0 += c[nt][0] + c[nt][1];
            l1 += c[nt][2] + c[nt][3];
        }
        #pragma unroll
        for (int ks2 = 0; ks2 < 4; ks2++) {
            unsigned ap[4];
            ap[0] = packbf(c[2 * ks2][0], c[2 * ks2][1]);
            ap[1] = packbf(c[2 * ks2][2], c[2 * ks2][3]);
            ap[2] = packbf(c[2 * ks2 + 1][0], c[2 * ks2 + 1][1]);
            ap[3] = packbf(c[2 * ks2 + 1][2], c[2 * ks2 + 1][3]);
            #pragma unroll
            for (int nt2 = 0; nt2 < 4; nt2++) {
                int d = nt2 * 8 + (lane >> 2);
                int k0 = ks2 * 16 + qc;
                unsigned bf[2];
                bf[0] = *(const unsigned*)&Vt[cur][d][k0];
                bf[1] = *(const unsigned*)&Vt[cur][d][k0 + 8];
                mma16816(o[nt2], ap, bf);
            }
        }

        if (t + 1 < NT) {
            int nxt = cur ^ 1;
            #pragma unroll
            for (int it = 0; it < 4; it++) {
                *(uint2*)&Ks[nxt][krow[it]][kcol[it]] = kreg[it];
                *(uint2*)&Vt[nxt][vrow[it]][vcol[it]] = vreg[it];
            }
            if (tid < 64) bias_s[nxt][tid] = breg;
        }
        __syncthreads();
    }

    l0 += __shfl_xor_sync(0xffffffffu, l0, 1);
    l0 += __shfl_xor_sync(0xffffffffu, l0, 2);
    l1 += __shfl_xor_sync(0xffffffffu, l1, 1);
    l1 += __shfl_xor_sync(0xffffffffu, l1, 2);

    float* dstO = g_attP + (((size_t)quarter * BB + b) * LQ + qr) * CC + h * HD;
    #pragma unroll
    for (int nt2 = 0; nt2 < 4; nt2++) {
        int c0 = nt2 * 8 + qc;
        *(float2*)&dstO[c0] = make_float2(o[nt2][0], o[nt2][1]);
        *(float2*)&dstO[(size_t)8 * CC + c0] = make_float2(o[nt2][2], o[nt2][3]);
    }
    if ((lane & 3) == 0) {
        size_t lidx = (((size_t)quarter * BB + b) * NHD + h) * LQ;
        g_lP[lidx + qr] = l0;
        g_lP[lidx + qr + 8] = l1;
    }
}

// ---------------- split-K merge (reads partials ONCE) ----------------
__global__ void attn_merge_kernel(__nv_bfloat16* __restrict__ attout) {
    int p = blockIdx.x * blockDim.x + threadIdx.x;
    const int PPR = CC / 2;
    int row = p / PPR, c2 = (p % PPR) * 2;
    int b = row / LQ, q = row % LQ;
    int h = c2 >> 5;
    float l = 0.f;
    #pragma unroll
    for (int s = 0; s < SPLITK; s++)
        l += g_lP[(((size_t)s * BB + b) * NHD + h) * LQ + q];
    float inv = 1.f / l;
    size_t oi = (size_t)row * CC + c2;
    float ox = 0.f, oy = 0.f;
    #pragma unroll
    for (int s = 0; s < SPLITK; s++) {
        float2 a = *(float2*)&g_attP[(size_t)s * BB * LQ * CC + oi];
        ox += a.x; oy += a.y;
    }
    ((unsigned*)attout)[p] = packbf(ox * inv, oy * inv);
}

// ---------------- launch (multi-branch graph) ----------------
extern "C" void kernel_launch(void* const* d_in, const int* in_sizes, int n_in,
                              void* d_out, int out_size) {
    const float* S_QP   = (const float*)d_in[0];
    const float* S_SM   = (const float*)d_in[1];
    const float* f_q    = (const float*)d_in[2];
    const float* P      = (const float*)d_in[3];
    const float* qp_W1  = (const float*)d_in[4];
    const float* qp_b1  = (const float*)d_in[5];
    const float* qp_W2  = (const float*)d_in[6];
    const float* qp_b2  = (const float*)d_in[7];
    const float* phiQ_W1 = (const float*)d_in[8];
    const float* phiQ_b1 = (const float*)d_in[9];
    const float* phiQ_W2 = (const float*)d_in[10];
    const float* phiQ_b2 = (const float*)d_in[11];
    const float* Wq = (const float*)d_in[12];
    const float* bq = (const float*)d_in[13];
    const float* Wk = (const float*)d_in[14];
    const float* bk = (const float*)d_in[15];
    const float* Wv = (const float*)d_in[16];
    const float* bv = (const float*)d_in[17];
    const float* Wo = (const float*)d_in[18];
    const float* bo = (const float*)d_in[19];
    const float* phi_W = (const float*)d_in[20];
    const float* phi_b = (const float*)d_in[21];
    float* out = (float*)d_out;

    float *p_sproj, *p_pp, *p_Wcomb, *p_bcomb;
    __nv_bfloat16 *p_hqb, *p_Qb, *p_fqT, *p_qb, *p_kb, *p_vT, *p_attb;
    cudaGetSymbolAddress((void**)&p_sproj, g_sproj);
    cudaGetSymbolAddress((void**)&p_pp, g_pp);
    cudaGetSymbolAddress((void**)&p_Wcomb, g_Wcomb);
    cudaGetSymbolAddress((void**)&p_bcomb, g_bcomb);
    cudaGetSymbolAddress((void**)&p_hqb, g_hqb);
    cudaGetSymbolAddress((void**)&p_Qb, g_Qb);
    cudaGetSymbolAddress((void**)&p_fqT, g_fqT);
    cudaGetSymbolAddress((void**)&p_qb, g_qb);
    cudaGetSymbolAddress((void**)&p_kb, g_kb);
    cudaGetSymbolAddress((void**)&p_vT, g_vT);
    cudaGetSymbolAddress((void**)&p_attb, g_attb);

    const float attnScale = 0.17677669529663687f;  // 1/sqrt(32)

    static cudaStream_t s1 = nullptr, s2 = nullptr, s3 = nullptr;
    static cudaEvent_t evRoot = nullptr, ev1 = nullptr, ev2 = nullptr, ev3 = nullptr;
    if (!s1) {
        cudaStreamCreateWithFlags(&s1, cudaStreamNonBlocking);
        cudaStreamCreateWithFlags(&s2, cudaStreamNonBlocking);
        cudaStreamCreateWithFlags(&s3, cudaStreamNonBlocking);
        cudaEventCreateWithFlags(&evRoot, cudaEventDisableTiming);
        cudaEventCreateWithFlags(&ev1, cudaEventDisableTiming);
        cudaEventCreateWithFlags(&ev2, cudaEventDisableTiming);
        cudaEventCreateWithFlags(&ev3, cudaEventDisableTiming);
    }

    cudaEventRecord(evRoot, 0);
    cudaStreamWaitEvent(s1, evRoot, 0);
    cudaStreamWaitEvent(s2, evRoot, 0);
    cudaStreamWaitEvent(s3, evRoot, 0);

    // ---- branch A (main): mean -> sproj(wide) -> tf32 hproj -> P_hat/V ----
    mean_partial_kernel<<<dim3(16, BB), 256>>>(S_SM);
    meansproj_kernel<<<dim3(BB, 8), 256>>>(qp_W1, qp_b1);
    gemm_tf32_hproj_kernel<<<dim3(64, 4, BB), 128>>>(
        f_q, (long)CC * LK, qp_W1 + (size_t)CC * CC, p_sproj, qp_W2, p_pp, LK);
    phat_final_kernel<<<(BB * LK) / 256, 256>>>(P, qp_b2, out);

    // ---- branch B (s1): transpose -> fused k/v ----
    transpose_fq_kernel<<<dim3(LK / 32, CC / 32, BB), 256, 0, s1>>>(f_q);
    hgemm_kv_kernel<<<dim3(64, 4, BB), 128, 0, s1>>>(
        p_fqT, (long)LK * CC, Wk, Wv, bk, bv,
        p_kb, (long)LK * CC, p_vT, (long)CC * LK, 4096, 256, 256);

    // ---- branch C (s2): hq -> Q -> q ----
    hgemm_cat_kernel<<<dim3(32, 4, 1), 128, 0, s2>>>(
        S_QP, S_SM, phiQ_W1, phiQ_b1, p_hqb, 2048, 256, 512);
    hgemm_kernel<0, 1><<<dim3(32, 4, 1), 128, 0, s2>>>(
        p_hqb, 0, phiQ_W2, CC, phiQ_b2, 0, nullptr,
        nullptr, p_Qb, 0, 1.f, 2048, 256, 256);
    hgemm_kernel<0, 1><<<dim3(32, 4, 1), 128, 0, s2>>>(
        p_Qb, 0, Wq, CC, bq, 0, nullptr,
        nullptr, p_qb, 0, attnScale, 2048, 256, 256);

    // ---- branch D (s3): Wcomb = Wo@phi_W ; bcomb (hidden under prologue+attention) ----
    wcomb_gemm_kernel<<<dim3(4, 4), 256, 0, s3>>>(Wo, phi_W);
    bcomb_kernel<<<1, 256, 0, s3>>>(phi_W, bo, phi_b);

    // join compute branches for attention
    cudaEventRecord(ev1, s1);
    cudaEventRecord(ev2, s2);
    cudaStreamWaitEvent(0, ev1, 0);
    cudaStreamWaitEvent(0, ev2, 0);

    // ---- tail: attention -> merge (reads partials once) -> single fused GEMM ----
    attn_mma_kernel<<<dim3(LQ / 64, NHD, BB * SPLITK), 128>>>(p_qb, p_kb, p_vT);
    attn_merge_kernel<<<(BB * LQ * CC / 2) / 256, 256>>>(p_attb);
    cudaEventRecord(ev3, s3);
    cudaStreamWaitEvent(0, ev3, 0);
    // out = S_SM - (attb @ Wcomb + bcomb)
    hgemm_kernel<2, 0><<<dim3(32, 4, 1), 128>>>(
        p_attb, 0, p_Wcomb, CC, p_bcomb, 0, S_SM,
        out, nullptr, 0, 1.f, 2048, 256, 256);
}

// round 16
// speedup vs baseline: 1.3883x; 1.0745x over previous
#include <cuda_runtime.h>
#include <cuda_bf16.h>
#include <math.h>

#define BB 2
#define LQ 1024
#define CC 256
#define LK 4096
#define NCH 2
#define NHD 8
#define HD 32
#define EPSV 1e-8f
#define SPLITK 4
#define LOG2E 1.4426950408889634f

// ---------------- scratch (device globals; no allocation) ----------------
__device__ float g_partialm[BB * 16 * CC];
__device__ float g_sproj[BB * CC];
__device__ float g_V2[BB * LK];                   // V * log2e (attention-side scratch)
__device__ float g_pp[4 * BB * LK * 2];           // per-n-block P_hat partials
__device__ float g_attP[SPLITK * BB * LQ * CC];   // split-K partial O (fp32)
__device__ float g_lP[SPLITK * BB * NHD * LQ];    // split-K partial row sums
__device__ float g_Wcomb[CC * CC];                // Wo @ phi_W
__device__ float g_bcomb[CC];                     // bo @ phi_W + phi_b
__device__ __nv_bfloat16 g_hqb[BB * LQ * CC];
__device__ __nv_bfloat16 g_Qb[BB * LQ * CC];
__device__ __nv_bfloat16 g_fqT[BB * LK * CC];   // f_q transposed, bf16 [b][Lk][C]
__device__ __nv_bfloat16 g_qb[BB * LQ * CC];    // q (scaled by attnScale*log2e) bf16
__device__ __nv_bfloat16 g_kb[BB * LK * CC];    // k bf16
__device__ __nv_bfloat16 g_vT[BB * CC * LK];    // v bf16 transposed [b][C][Lk]
__device__ __nv_bfloat16 g_attb[BB * LQ * CC];  // merged attention, bf16

__device__ __forceinline__ unsigned packbf(float x, float y) {
    __nv_bfloat162 h = __floats2bfloat162_rn(x, y);
    return *(unsigned*)&h;
}
__device__ __forceinline__ unsigned f2tf(float x) {
    unsigned r;
    asm("cvt.rna.tf32.f32 %0, %1;" : "=r"(r) : "f"(x));
    return r;
}
__device__ __forceinline__ float fast_ex2(float x) {
    float y;
    asm("ex2.approx.ftz.f32 %0, %1;" : "=f"(y) : "f"(x));
    return y;
}

// ---------------- mean of S_SM over Lq (stage 1) ----------------
__global__ void mean_partial_kernel(const float* __restrict__ S_SM) {
    int b = blockIdx.y, seg = blockIdx.x, c = threadIdx.x;
    const float* base = S_SM + ((size_t)b * LQ + (size_t)seg * 64) * CC + c;
    float acc = 0.f;
    #pragma unroll 8
    for (int l = 0; l < 64; l++) acc += base[(size_t)l * CC];
    g_partialm[(b * 16 + seg) * CC + c] = acc;
}

// ---------------- fused: mean finalize + sproj (wide: grid BB x 8) ----------------
__global__ void meansproj_kernel(const float* __restrict__ qp_W1,
                                 const float* __restrict__ qp_b1) {
    __shared__ float smean[CC];
    int b = blockIdx.x, seg = blockIdx.y;
    int tid = threadIdx.x;
    {
        float acc = 0.f;
        #pragma unroll
        for (int s = 0; s < 16; s++) acc += g_partialm[(b * 16 + s) * CC + tid];
        smean[tid] = acc * (1.0f / LQ);
    }
    __syncthreads();
    int n = seg * 32 + (tid >> 3);
    int cp = tid & 7;
    float acc = 0.f;
    for (int c = cp; c < CC; c += 8) acc += smean[c] * qp_W1[(size_t)c * CC + n];
    acc += __shfl_down_sync(0xffffffffu, acc, 4, 8);
    acc += __shfl_down_sync(0xffffffffu, acc, 2, 8);
    acc += __shfl_down_sync(0xffffffffu, acc, 1, 8);
    if (cp == 0) g_sproj[b * CC + n] = qp_b1[n] + acc;
}

// ---------------- Wcomb = Wo @ phi_W (fp32 tiled; runs concurrently on s3) ---------
__global__ __launch_bounds__(256)
void wcomb_gemm_kernel(const float* __restrict__ Wo, const float* __restrict__ phiW) {
    const int BM = 64, BN = 64, BK = 16;
    __shared__ __align__(16) float As[BK][BM];
    __shared__ __align__(16) float Bs[BK][BN];
    int m0 = blockIdx.x * BM, n0 = blockIdx.y * BN;
    int t = threadIdx.x;
    int tx = t % 16, ty = t / 16;
    float acc[4][4];
    #pragma unroll
    for (int i = 0; i < 4; i++)
        #pragma unroll
        for (int j = 0; j < 4; j++) acc[i][j] = 0.f;
    for (int k0 = 0; k0 < CC; k0 += BK) {
        {
            int mm = t / 4, kk4 = (t % 4) * 4;
            float4 av = *(const float4*)&Wo[(size_t)(m0 + mm) * CC + k0 + kk4];
            As[kk4 + 0][mm] = av.x; As[kk4 + 1][mm] = av.y;
            As[kk4 + 2][mm] = av.z; As[kk4 + 3][mm] = av.w;
        }
        {
            int kk = t / 16, nn4 = (t % 16) * 4;
            *(float4*)&Bs[kk][nn4] = *(const float4*)&phiW[(size_t)(k0 + kk) * CC + n0 + nn4];
        }
        __syncthreads();
        #pragma unroll
        for (int kk = 0; kk < BK; kk++) {
            float4 a4 = *(const float4*)&As[kk][ty * 4];
            float4 b4 = *(const float4*)&Bs[kk][tx * 4];
            float a[4] = {a4.x, a4.y, a4.z, a4.w};
            float b[4] = {b4.x, b4.y, b4.z, b4.w};
            #pragma unroll
            for (int i = 0; i < 4; i++)
                #pragma unroll
                for (int j = 0; j < 4; j++) acc[i][j] += a[i] * b[j];
        }
        __syncthreads();
    }
    #pragma unroll
    for (int i = 0; i < 4; i++)
        #pragma unroll
        for (int j = 0; j < 4; j++)
            g_Wcomb[(size_t)(m0 + ty * 4 + i) * CC + n0 + tx * 4 + j] = acc[i][j];
}

__global__ void bcomb_kernel(const float* __restrict__ phiW,
                             const float* __restrict__ bo,
                             const float* __restrict__ phi_b) {
    int n = threadIdx.x;
    float acc = phi_b[n];
    for (int c = 0; c < CC; c++) acc += bo[c] * phiW[(size_t)c * CC + n];
    g_bcomb[n] = acc;
}

// ---------------- f_q [b][C][Lk] fp32 -> fqT [b][Lk][C] bf16 ----------------
__global__ void transpose_fq_kernel(const float* __restrict__ f_q) {
    __shared__ float tile[32][33];
    int b = blockIdx.z;
    int l0 = blockIdx.x * 32, c0 = blockIdx.y * 32;
    int tx = threadIdx.x & 31, ty = threadIdx.x >> 5;
    const float* src = f_q + ((size_t)b * CC + c0) * LK + l0;
    #pragma unroll
    for (int j = 0; j < 4; j++) tile[ty + 8 * j][tx] = src[(size_t)(ty + 8 * j) * LK + tx];
    __syncthreads();
    unsigned* dst = (unsigned*)(g_fqT + ((size_t)b * LK + l0) * CC + c0);
    #pragma unroll
    for (int it = 0; it < 2; it++) {
        int i = threadIdx.x + it * 256;
        int r = i >> 4, p = i & 15;
        dst[(size_t)r * (CC / 2) + p] = packbf(tile[2 * p][r], tile[2 * p + 1][r]);
    }
}

// ---------------- tf32 tensor-core GEMM for h, with fused P_hat projection ----------
__global__ __launch_bounds__(128)
void gemm_tf32_hproj_kernel(const float* __restrict__ A, long strideA,
                            const float* __restrict__ W,
                            const float* __restrict__ bias,
                            const float* __restrict__ W2,
                            float* __restrict__ pp, int lda) {
    __shared__ unsigned As2[32][72];
    __shared__ unsigned Bs2[32][72];
    __shared__ float w2s[64][2];
    __shared__ float sred[2][2][64];

    int bz = blockIdx.z;
    A += (size_t)bz * strideA;
    const float* biasP = bias + (size_t)bz * CC;
    int m0 = blockIdx.x * 64, n0 = blockIdx.y * 64;
    int tid = threadIdx.x, warp = tid >> 5, lane = tid & 31;
    int wm = warp & 1, wn = warp >> 1;
    int qr = lane >> 2, ql = lane & 3;

    if (tid < 64) {
        w2s[tid][0] = W2[(size_t)(n0 + tid) * 2 + 0];
        w2s[tid][1] = W2[(size_t)(n0 + tid) * 2 + 1];
    }

    float c[2][4][4];
    #pragma unroll
    for (int i = 0; i < 2; i++)
        #pragma unroll
        for (int j = 0; j < 4; j++)
            #pragma unroll
            for (int r = 0; r < 4; r++) c[i][j][r] = 0.f;

    for (int k0 = 0; k0 < CC; k0 += 32) {
        #pragma unroll
        for (int it = 0; it < 4; it++) {
            int i = tid + it * 128;
            int kk = i >> 4, m4 = (i & 15) * 4;
            float4 av = *(const float4*)&A[(size_t)(k0 + kk) * lda + m0 + m4];
            As2[kk][m4 + 0] = f2tf(av.x);
            As2[kk][m4 + 1] = f2tf(av.y);
            As2[kk][m4 + 2] = f2tf(av.z);
            As2[kk][m4 + 3] = f2tf(av.w);
        }
        #pragma unroll
        for (int it = 0; it < 4; it++) {
            int i = tid + it * 128;
            int kk = i >> 4, n4 = (i & 15) * 4;
            float4 wv = *(const float4*)&W[(size_t)(k0 + kk) * CC + n0 + n4];
            Bs2[kk][n4 + 0] = f2tf(wv.x);
            Bs2[kk][n4 + 1] = f2tf(wv.y);
            Bs2[kk][n4 + 2] = f2tf(wv.z);
            Bs2[kk][n4 + 3] = f2tf(wv.w);
        }
        __syncthreads();
        #pragma unroll
        for (int kk = 0; kk < 32; kk += 8) {
            unsigned a[2][4], b[4][2];
            #pragma unroll
            for (int i = 0; i < 2; i++) {
                int r = wm * 32 + i * 16 + qr;
                a[i][0] = As2[kk + ql][r];
                a[i][1] = As2[kk + ql][r + 8];
                a[i][2] = As2[kk + ql + 4][r];
                a[i][3] = As2[kk + ql + 4][r + 8];
            }
            #pragma unroll
            for (int j = 0; j < 4; j++) {
                int n = wn * 32 + j * 8 + qr;
                b[j][0] = Bs2[kk + ql][n];
                b[j][1] = Bs2[kk + ql + 4][n];
            }
            #pragma unroll
            for (int i = 0; i < 2; i++)
                #pragma unroll
                for (int j = 0; j < 4; j++)
                    asm volatile(
                        "mma.sync.aligned.m16n8k8.row.col.f32.tf32.tf32.f32 "
                        "{%0,%1,%2,%3}, {%4,%5,%6,%7}, {%8,%9}, {%0,%1,%2,%3};\n"
                        : "+f"(c[i][j][0]), "+f"(c[i][j][1]), "+f"(c[i][j][2]), "+f"(c[i][j][3])
                        : "r"(a[i][0]), "r"(a[i][1]), "r"(a[i][2]), "r"(a[i][3]),
                          "r"(b[j][0]), "r"(b[j][1]));
        }
        __syncthreads();
    }

    float p[2][4];
    #pragma unroll
    for (int ch = 0; ch < 2; ch++)
        #pragma unroll
        for (int s = 0; s < 4; s++) p[ch][s] = 0.f;
    #pragma unroll
    for (int i = 0; i < 2; i++) {
        #pragma unroll
        for (int j = 0; j < 4; j++) {
            int n = wn * 32 + j * 8 + 2 * ql;
            float b0 = biasP[n0 + n], b1 = biasP[n0 + n + 1];
            float h00 = fmaxf(c[i][j][0] + b0, 0.f);
            float h01 = fmaxf(c[i][j][1] + b1, 0.f);
            float h10 = fmaxf(c[i][j][2] + b0, 0.f);
            float h11 = fmaxf(c[i][j][3] + b1, 0.f);
            float wa0 = w2s[n][0], wb0 = w2s[n + 1][0];
            float wa1 = w2s[n][1], wb1 = w2s[n + 1][1];
            p[0][i * 2 + 0] += h00 * wa0 + h01 * wb0;
            p[1][i * 2 + 0] += h00 * wa1 + h01 * wb1;
            p[0][i * 2 + 1] += h10 * wa0 + h11 * wb0;
            p[1][i * 2 + 1] += h10 * wa1 + h11 * wb1;
        }
    }
    #pragma unroll
    for (int ch = 0; ch < 2; ch++)
        #pragma unroll
        for (int s = 0; s < 4; s++) {
            p[ch][s] += __shfl_xor_sync(0xffffffffu, p[ch][s], 1);
            p[ch][s] += __shfl_xor_sync(0xffffffffu, p[ch][s], 2);
        }
    if (ql == 0) {
        #pragma unroll
        for (int ch = 0; ch < 2; ch++)
            #pragma unroll
            for (int s = 0; s < 4; s++)
                sred[wn][ch][wm * 32 + s * 8 + qr] = p[ch][s];
    }
    __syncthreads();
    {
        int ch = tid >> 6, row = tid & 63;
        float v = sred[0][ch][row] + sred[1][ch][row];
        pp[(((size_t)blockIdx.y * BB + bz) * LK + m0 + row) * 2 + ch] = v;
    }
}

// ---------------- finalize P_hat + entropy + V ----------------
__device__ __forceinline__ float ent2(float x0, float x1) {
    float d = x0 - x1;
    float p0 = 1.f / (1.f + expf(-d));
    float p1 = 1.f / (1.f + expf(d));
    p0 = fmaxf(p0, EPSV);
    p1 = fmaxf(p1, EPSV);
    return -(p0 * logf(p0) + p1 * logf(p1));
}

__global__ void phat_final_kernel(const float* __restrict__ P,
                                  const float* __restrict__ qp_b2,
                                  float* __restrict__ out) {
    int idx = blockIdx.x * blockDim.x + threadIdx.x;
    if (idx >= BB * LK) return;
    int b = idx / LK, pix = idx % LK;
    float ph0 = qp_b2[0], ph1 = qp_b2[1];
    #pragma unroll
    for (int nb = 0; nb < 4; nb++) {
        float2 pv = *(const float2*)&g_pp[(((size_t)nb * BB + b) * LK + pix) * 2];
        ph0 += pv.x; ph1 += pv.y;
    }
    float* phat = out + (size_t)BB * LQ * CC;
    phat[((size_t)b * NCH + 0) * LK + pix] = ph0;
    phat[((size_t)b * NCH + 1) * LK + pix] = ph1;
    float p0 = P[((size_t)b * NCH + 0) * LK + pix];
    float p1 = P[((size_t)b * NCH + 1) * LK + pix];
    float Vv = ent2(ph0, ph1) - ent2(p0, p1);
    float* vout = out + (size_t)BB * LQ * CC + (size_t)BB * NCH * LK;
    vout[(size_t)b * LK + pix] = Vv;            // exact output value
    g_V2[b * LK + pix] = Vv * LOG2E;            // log2-domain scratch for attention
}

// ---------------- bf16 HMMA helpers ----------------
__device__ __forceinline__ void mma16816(float* c, const unsigned* a, const unsigned* b) {
    asm volatile(
        "mma.sync.aligned.m16n8k16.row.col.f32.bf16.bf16.f32 "
        "{%0,%1,%2,%3}, {%4,%5,%6,%7}, {%8,%9}, {%0,%1,%2,%3};\n"
        : "+f"(c[0]), "+f"(c[1]), "+f"(c[2]), "+f"(c[3])
        : "r"(a[0]), "r"(a[1]), "r"(a[2]), "r"(a[3]), "r"(b[0]), "r"(b[1]));
}

// ---------------- bf16 tensor-core GEMM ----------------
// EPI: 0 bias, 1 bias+relu, 2 Dsub - (acc+bias)
// OUTMODE: 0 fp32 row-major, 1 bf16 row-major (*outScale)
template <int EPI, int OUTMODE>
__global__ __launch_bounds__(128)
void hgemm_kernel(const __nv_bfloat16* __restrict__ A, long strideA,
                  const float* __restrict__ W, int ldw,
                  const float* __restrict__ bias, int biasStride,
                  const float* __restrict__ Dsub,
                  float* __restrict__ CoutF, __nv_bfloat16* __restrict__ CoutB,
                  long strideC, float outScale,
                  int M, int N, int K) {
    __shared__ __align__(16) __nv_bfloat16 As[64][40];
    __shared__ __align__(16) __nv_bfloat16 Bs[64][40];

    int bz = blockIdx.z;
    A += (size_t)bz * strideA;
    if (OUTMODE == 0) CoutF += (size_t)bz * strideC;
    else              CoutB += (size_t)bz * strideC;
    const float* biasP = bias + (size_t)bz * biasStride;

    int m0 = blockIdx.x * 64, n0 = blockIdx.y * 64;
    int tid = threadIdx.x, warp = tid >> 5, lane = tid & 31;
    int wm = warp & 1, wn = warp >> 1;
    int qrow = lane >> 2, qc2 = (lane & 3) * 2;

    float c[2][4][4];
    #pragma unroll
    for (int i = 0; i < 2; i++)
        #pragma unroll
        for (int j = 0; j < 4; j++)
            #pragma unroll
            for (int r = 0; r < 4; r++) c[i][j][r] = 0.f;

    for (int k0 = 0; k0 < K; k0 += 32) {
        #pragma unroll
        for (int it = 0; it < 2; it++) {
            int i = tid + it * 128;
            int row = i >> 2, seg = i & 3;
            *(uint4*)&As[row][seg * 8] =
                *(const uint4*)(A + (size_t)(m0 + row) * K + k0 + seg * 8);
        }
        #pragma unroll
        for (int it = 0; it < 4; it++) {
            int i = tid + it * 128;
            int kk = i >> 4, n4 = (i & 15) * 4;
            float4 wv = *(const float4*)(W + (size_t)(k0 + kk) * ldw + n0 + n4);
            Bs[n4 + 0][kk] = __float2bfloat16_rn(wv.x);
            Bs[n4 + 1][kk] = __float2bfloat16_rn(wv.y);
            Bs[n4 + 2][kk] = __float2bfloat16_rn(wv.z);
            Bs[n4 + 3][kk] = __float2bfloat16_rn(wv.w);
        }
        __syncthreads();
        #pragma unroll
        for (int kk = 0; kk < 32; kk += 16) {
            unsigned a[2][4], bfr[4][2];
            #pragma unroll
            for (int i = 0; i < 2; i++) {
                int r = wm * 32 + i * 16 + qrow;
                a[i][0] = *(const unsigned*)&As[r][kk + qc2];
                a[i][1] = *(const unsigned*)&As[r + 8][kk + qc2];
                a[i][2] = *(const unsigned*)&As[r][kk + qc2 + 8];
                a[i][3] = *(const unsigned*)&As[r + 8][kk + qc2 + 8];
            }
            #pragma unroll
            for (int j = 0; j < 4; j++) {
                int n = wn * 32 + j * 8 + qrow;
                bfr[j][0] = *(const unsigned*)&Bs[n][kk + qc2];
                bfr[j][1] = *(const unsigned*)&Bs[n][kk + qc2 + 8];
            }
            #pragma unroll
            for (int i = 0; i < 2; i++)
                #pragma unroll
                for (int j = 0; j < 4; j++) mma16816(c[i][j], a[i], bfr[j]);
        }
        __syncthreads();
    }

    #pragma unroll
    for (int i = 0; i < 2; i++) {
        #pragma unroll
        for (int j = 0; j < 4; j++) {
            int m = m0 + wm * 32 + i * 16 + qrow;
            int n = n0 + wn * 32 + j * 8 + qc2;
            float b0 = biasP[n], b1 = biasP[n + 1];
            float v0 = c[i][j][0] + b0, v1 = c[i][j][1] + b1;
            float v2 = c[i][j][2] + b0, v3 = c[i][j][3] + b1;
            if (EPI == 1) {
                v0 = fmaxf(v0, 0.f); v1 = fmaxf(v1, 0.f);
                v2 = fmaxf(v2, 0.f); v3 = fmaxf(v3, 0.f);
            }
            if (EPI == 2) {
                v0 = Dsub[(size_t)m * N + n] - v0;
                v1 = Dsub[(size_t)m * N + n + 1] - v1;
                v2 = Dsub[(size_t)(m + 8) * N + n] - v2;
                v3 = Dsub[(size_t)(m + 8) * N + n + 1] - v3;
            }
            if (OUTMODE == 0) {
                *(float2*)&CoutF[(size_t)m * N + n] = make_float2(v0, v1);
                *(float2*)&CoutF[(size_t)(m + 8) * N + n] = make_float2(v2, v3);
            } else {
                *(unsigned*)&CoutB[(size_t)m * N + n] = packbf(v0 * outScale, v1 * outScale);
                *(unsigned*)&CoutB[(size_t)(m + 8) * N + n] = packbf(v2 * outScale, v3 * outScale);
            }
        }
    }
}

// ---------------- fused k/v GEMM ----------------
__global__ __launch_bounds__(128)
void hgemm_kv_kernel(const __nv_bfloat16* __restrict__ A, long strideA,
                     const float* __restrict__ Wk, const float* __restrict__ Wv,
                     const float* __restrict__ bk, const float* __restrict__ bv,
                     __nv_bfloat16* __restrict__ Kout, long strideK,
                     __nv_bfloat16* __restrict__ Vout, long strideV,
                     int M, int N, int K) {
    __shared__ __align__(16) __nv_bfloat16 As[64][40];
    __shared__ __align__(16) __nv_bfloat16 Bsk[64][40];
    __shared__ __align__(16) __nv_bfloat16 Bsv[64][40];

    int bz = blockIdx.z;
    A += (size_t)bz * strideA;
    Kout += (size_t)bz * strideK;
    Vout += (size_t)bz * strideV;

    int m0 = blockIdx.x * 64, n0 = blockIdx.y * 64;
    int tid = threadIdx.x, warp = tid >> 5, lane = tid & 31;
    int wm = warp & 1, wn = warp >> 1;
    int qrow = lane >> 2, qc2 = (lane & 3) * 2;

    float ck[2][4][4], cv[2][4][4];
    #pragma unroll
    for (int i = 0; i < 2; i++)
        #pragma unroll
        for (int j = 0; j < 4; j++)
            #pragma unroll
            for (int r = 0; r < 4; r++) { ck[i][j][r] = 0.f; cv[i][j][r] = 0.f; }

    for (int k0 = 0; k0 < K; k0 += 32) {
        #pragma unroll
        for (int it = 0; it < 2; it++) {
            int i = tid + it * 128;
            int row = i >> 2, seg = i & 3;
            *(uint4*)&As[row][seg * 8] =
                *(const uint4*)(A + (size_t)(m0 + row) * K + k0 + seg * 8);
        }
        #pragma unroll
        for (int it = 0; it < 4; it++) {
            int i = tid + it * 128;
            int kk = i >> 4, n4 = (i & 15) * 4;
            float4 wv1 = *(const float4*)(Wk + (size_t)(k0 + kk) * N + n0 + n4);
            float4 wv2 = *(const float4*)(Wv + (size_t)(k0 + kk) * N + n0 + n4);
            Bsk[n4 + 0][kk] = __float2bfloat16_rn(wv1.x);
            Bsk[n4 + 1][kk] = __float2bfloat16_rn(wv1.y);
            Bsk[n4 + 2][kk] = __float2bfloat16_rn(wv1.z);
            Bsk[n4 + 3][kk] = __float2bfloat16_rn(wv1.w);
            Bsv[n4 + 0][kk] = __float2bfloat16_rn(wv2.x);
            Bsv[n4 + 1][kk] = __float2bfloat16_rn(wv2.y);
            Bsv[n4 + 2][kk] = __float2bfloat16_rn(wv2.z);
            Bsv[n4 + 3][kk] = __float2bfloat16_rn(wv2.w);
        }
        __syncthreads();
        #pragma unroll
        for (int kk = 0; kk < 32; kk += 16) {
            unsigned a[2][4], bk_f[4][2], bv_f[4][2];
            #pragma unroll
            for (int i = 0; i < 2; i++) {
                int r = wm * 32 + i * 16 + qrow;
                a[i][0] = *(const unsigned*)&As[r][kk + qc2];
                a[i][1] = *(const unsigned*)&As[r + 8][kk + qc2];
                a[i][2] = *(const unsigned*)&As[r][kk + qc2 + 8];
                a[i][3] = *(const unsigned*)&As[r + 8][kk + qc2 + 8];
            }
            #pragma unroll
            for (int j = 0; j < 4; j++) {
                int n = wn * 32 + j * 8 + qrow;
                bk_f[j][0] = *(const unsigned*)&Bsk[n][kk + qc2];
                bk_f[j][1] = *(const unsigned*)&Bsk[n][kk + qc2 + 8];
                bv_f[j][0] = *(const unsigned*)&Bsv[n][kk + qc2];
                bv_f[j][1] = *(const unsigned*)&Bsv[n][kk + qc2 + 8];
            }
            #pragma unroll
            for (int i = 0; i < 2; i++)
                #pragma unroll
                for (int j = 0; j < 4; j++) {
                    mma16816(ck[i][j], a[i], bk_f[j]);
                    mma16816(cv[i][j], a[i], bv_f[j]);
                }
        }
        __syncthreads();
    }

    #pragma unroll
    for (int i = 0; i < 2; i++) {
        #pragma unroll
        for (int j = 0; j < 4; j++) {
            int m = m0 + wm * 32 + i * 16 + qrow;
            int n = n0 + wn * 32 + j * 8 + qc2;
            float kb0 = bk[n], kb1 = bk[n + 1];
            float vb0 = bv[n], vb1 = bv[n + 1];
            *(unsigned*)&Kout[(size_t)m * N + n] = packbf(ck[i][j][0] + kb0, ck[i][j][1] + kb1);
            *(unsigned*)&Kout[(size_t)(m + 8) * N + n] = packbf(ck[i][j][2] + kb0, ck[i][j][3] + kb1);
            Vout[(size_t)n * M + m] = __float2bfloat16_rn(cv[i][j][0] + vb0);
            Vout[(size_t)(n + 1) * M + m] = __float2bfloat16_rn(cv[i][j][1] + vb1);
            Vout[(size_t)n * M + m + 8] = __float2bfloat16_rn(cv[i][j][2] + vb0);
            Vout[(size_t)(n + 1) * M + m + 8] = __float2bfloat16_rn(cv[i][j][3] + vb1);
        }
    }
}

// ---------------- bf16 HMMA GEMM with concatenated fp32 A = [A0 | A1] ----------------
__global__ __launch_bounds__(128)
void hgemm_cat_kernel(const float* __restrict__ A0, const float* __restrict__ A1,
                      const float* __restrict__ W,
                      const float* __restrict__ bias,
                      __nv_bfloat16* __restrict__ CoutB,
                      int M, int N, int K) {
    __shared__ __align__(16) __nv_bfloat16 As[64][40];
    __shared__ __align__(16) __nv_bfloat16 Bs[64][40];

    int m0 = blockIdx.x * 64, n0 = blockIdx.y * 64;
    int tid = threadIdx.x, warp = tid >> 5, lane = tid & 31;
    int wm = warp & 1, wn = warp >> 1;
    int qrow = lane >> 2, qc2 = (lane & 3) * 2;

    float c[2][4][4];
    #pragma unroll
    for (int i = 0; i < 2; i++)
        #pragma unroll
        for (int j = 0; j < 4; j++)
            #pragma unroll
            for (int r = 0; r < 4; r++) c[i][j][r] = 0.f;

    for (int k0 = 0; k0 < K; k0 += 32) {
        const float* Asrc = (k0 < CC) ? A0 : A1;
        int kloc = (k0 < CC) ? k0 : k0 - CC;
        #pragma unroll
        for (int it = 0; it < 4; it++) {
            int i = tid + it * 128;
            int row = i >> 3, seg = i & 7;
            float4 av = *(const float4*)&Asrc[(size_t)(m0 + row) * CC + kloc + seg * 4];
            As[row][seg * 4 + 0] = __float2bfloat16_rn(av.x);
            As[row][seg * 4 + 1] = __float2bfloat16_rn(av.y);
            As[row][seg * 4 + 2] = __float2bfloat16_rn(av.z);
            As[row][seg * 4 + 3] = __float2bfloat16_rn(av.w);
        }
        #pragma unroll
        for (int it = 0; it < 4; it++) {
            int i = tid + it * 128;
            int kk = i >> 4, n4 = (i & 15) * 4;
            float4 wv = *(const float4*)(W + (size_t)(k0 + kk) * N + n0 + n4);
            Bs[n4 + 0][kk] = __float2bfloat16_rn(wv.x);
            Bs[n4 + 1][kk] = __float2bfloat16_rn(wv.y);
            Bs[n4 + 2][kk] = __float2bfloat16_rn(wv.z);
            Bs[n4 + 3][kk] = __float2bfloat16_rn(wv.w);
        }
        __syncthreads();
        #pragma unroll
        for (int kk = 0; kk < 32; kk += 16) {
            unsigned a[2][4], bfr[4][2];
            #pragma unroll
            for (int i = 0; i < 2; i++) {
                int r = wm * 32 + i * 16 + qrow;
                a[i][0] = *(const unsigned*)&As[r][kk + qc2];
                a[i][1] = *(const unsigned*)&As[r + 8][kk + qc2];
                a[i][2] = *(const unsigned*)&As[r][kk + qc2 + 8];
                a[i][3] = *(const unsigned*)&As[r + 8][kk + qc2 + 8];
            }
            #pragma unroll
            for (int j = 0; j < 4; j++) {
                int n = wn * 32 + j * 8 + qrow;
                bfr[j][0] = *(const unsigned*)&Bs[n][kk + qc2];
                bfr[j][1] = *(const unsigned*)&Bs[n][kk + qc2 + 8];
            }
            #pragma unroll
            for (int i = 0; i < 2; i++)
                #pragma unroll
                for (int j = 0; j < 4; j++) mma16816(c[i][j], a[i], bfr[j]);
        }
        __syncthreads();
    }

    #pragma unroll
    for (int i = 0; i < 2; i++) {
        #pragma unroll
        for (int j = 0; j < 4; j++) {
            int m = m0 + wm * 32 + i * 16 + qrow;
            int n = n0 + wn * 32 + j * 8 + qc2;
            float b0 = bias[n], b1 = bias[n + 1];
            float v0 = fmaxf(c[i][j][0] + b0, 0.f), v1 = fmaxf(c[i][j][1] + b1, 0.f);
            float v2 = fmaxf(c[i][j][2] + b0, 0.f), v3 = fmaxf(c[i][j][3] + b1, 0.f);
            *(unsigned*)&CoutB[(size_t)m * N + n] = packbf(v0, v1);
            *(unsigned*)&CoutB[(size_t)(m + 8) * N + n] = packbf(v2, v3);
        }
    }
}

// ---------------- bf16 tensor-core attention (double-buffered, split-K x4) ----------------
// Log2-domain softmax: q pre-scaled by attnScale*log2e, bias scratch pre-scaled
// by log2e; p = 2^(s + b) via ex2.approx (== __expf result, minus the FMUL).
__global__ __launch_bounds__(128)
void attn_mma_kernel(const __nv_bfloat16* __restrict__ qb,
                     const __nv_bfloat16* __restrict__ kb,
                     const __nv_bfloat16* __restrict__ vT) {
    __shared__ __align__(16) __nv_bfloat16 Ks[2][64][40];
    __shared__ __align__(16) __nv_bfloat16 Vt[2][32][72];
    __shared__ float bias_s[2][64];

    int qt = blockIdx.x, h = blockIdx.y;
    int b = blockIdx.z >> 2, quarter = blockIdx.z & 3;
    int tid = threadIdx.x, warp = tid >> 5, lane = tid & 31;
    int qr = qt * 64 + warp * 16 + (lane >> 2);
    int qc = (lane & 3) * 2;
    const int HK = LK / SPLITK;
    int kofs = quarter * HK;

    const __nv_bfloat16* kbase[4];
    const __nv_bfloat16* vbase[4];
    int krow[4], kcol[4], vrow[4], vcol[4];
    #pragma unroll
    for (int it = 0; it < 4; it++) {
        int i = tid + it * 128;
        krow[it] = i >> 3; kcol[it] = (i & 7) * 4;
        kbase[it] = kb + ((size_t)(b * LK) + kofs + krow[it]) * CC + h * HD + kcol[it];
        vrow[it] = i >> 4; vcol[it] = (i & 15) * 4;
        vbase[it] = vT + ((size_t)b * CC + h * HD + vrow[it]) * LK + kofs + vcol[it];
    }
    const float* vbias = g_V2 + b * LK + kofs + tid;

    unsigned aq[2][4];
    const __nv_bfloat16* qbase = qb + ((size_t)(b * LQ) + qr) * CC + h * HD;
    #pragma unroll
    for (int ks = 0; ks < 2; ks++) {
        aq[ks][0] = *(const unsigned*)(qbase + ks * 16 + qc);
        aq[ks][1] = *(const unsigned*)(qbase + (size_t)8 * CC + ks * 16 + qc);
        aq[ks][2] = *(const unsigned*)(qbase + ks * 16 + qc + 8);
        aq[ks][3] = *(const unsigned*)(qbase + (size_t)8 * CC + ks * 16 + qc + 8);
    }

    float o[4][4];
    #pragma unroll
    for (int i = 0; i < 4; i++)
        #pragma unroll
        for (int j = 0; j < 4; j++) o[i][j] = 0.f;
    float l0 = 0.f, l1 = 0.f;

    uint2 kreg[4], vreg[4];
    float breg = 0.f;
    #pragma unroll
    for (int it = 0; it < 4; it++) {
        kreg[it] = *(const uint2*)(kbase[it]);
        vreg[it] = *(const uint2*)(vbase[it]);
    }
    if (tid < 64) breg = vbias[0];
    #pragma unroll
    for (int it = 0; it < 4; it++) {
        *(uint2*)&Ks[0][krow[it]][kcol[it]] = kreg[it];
        *(uint2*)&Vt[0][vrow[it]][vcol[it]] = vreg[it];
    }
    if (tid < 64) bias_s[0][tid] = breg;
    __syncthreads();

    const int NT = HK / 64;
    for (int t = 0; t < NT; t++) {
        int cur = t & 1;
        if (t + 1 < NT) {
            int off = (t + 1) * 64;
            #pragma unroll
            for (int it = 0; it < 4; it++) {
                kreg[it] = *(const uint2*)(kbase[it] + (size_t)off * CC);
                vreg[it] = *(const uint2*)(vbase[it] + off);
            }
            if (tid < 64) breg = vbias[off];
        }

        float c[8][4];
        #pragma unroll
        for (int nt = 0; nt < 8; nt++) {
            c[nt][0] = c[nt][1] = c[nt][2] = c[nt][3] = 0.f;
            int n = nt * 8 + (lane >> 2);
            #pragma unroll
            for (int ks = 0; ks < 2; ks++) {
                unsigned bf[2];
                int k0 = ks * 16 + qc;
                bf[0] = *(const unsigned*)&Ks[cur][n][k0];
                bf[1] = *(const unsigned*)&Ks[cur][n][k0 + 8];
                mma16816(c[nt], aq[ks], bf);
            }
        }
        #pragma unroll
        for (int nt = 0; nt < 8; nt++) {
            float b0 = bias_s[cur][nt * 8 + qc], b1 = bias_s[cur][nt * 8 + qc + 1];
            c[nt][0] = fast_ex2(c[nt][0] + b0);
            c[nt][1] = fast_ex2(c[nt][1] + b1);
            c[nt][2] = fast_ex2(c[nt][2] + b0);
            c[nt][3] = fast_ex2(c[nt][3] + b1);
            l0 += c[nt][0] + c[nt][1];
            l1 += c[nt][2] + c[nt][3];
        }
        #pragma unroll
        for (int ks2 = 0; ks2 < 4; ks2++) {
            unsigned ap[4];
            ap[0] = packbf(c[2 * ks2][0], c[2 * ks2][1]);
            ap[1] = packbf(c[2 * ks2][2], c[2 * ks2][3]);
            ap[2] = packbf(c[2 * ks2 + 1][0], c[2 * ks2 + 1][1]);
            ap[3] = packbf(c[2 * ks2 + 1][2], c[2 * ks2 + 1][3]);
            #pragma unroll
            for (int nt2 = 0; nt2 < 4; nt2++) {
                int d = nt2 * 8 + (lane >> 2);
                int k0 = ks2 * 16 + qc;
                unsigned bf[2];
                bf[0] = *(const unsigned*)&Vt[cur][d][k0];
                bf[1] = *(const unsigned*)&Vt[cur][d][k0 + 8];
                mma16816(o[nt2], ap, bf);
            }
        }

        if (t + 1 < NT) {
            int nxt = cur ^ 1;
            #pragma unroll
            for (int it = 0; it < 4; it++) {
                *(uint2*)&Ks[nxt][krow[it]][kcol[it]] = kreg[it];
                *(uint2*)&Vt[nxt][vrow[it]][vcol[it]] = vreg[it];
            }
            if (tid < 64) bias_s[nxt][tid] = breg;
        }
        __syncthreads();
    }

    l0 += __shfl_xor_sync(0xffffffffu, l0, 1);
    l0 += __shfl_xor_sync(0xffffffffu, l0, 2);
    l1 += __shfl_xor_sync(0xffffffffu, l1, 1);
    l1 += __shfl_xor_sync(0xffffffffu, l1, 2);

    float* dstO = g_attP + (((size_t)quarter * BB + b) * LQ + qr) * CC + h * HD;
    #pragma unroll
    for (int nt2 = 0; nt2 < 4; nt2++) {
        int c0 = nt2 * 8 + qc;
        *(float2*)&dstO[c0] = make_float2(o[nt2][0], o[nt2][1]);
        *(float2*)&dstO[(size_t)8 * CC + c0] = make_float2(o[nt2][2], o[nt2][3]);
    }
    if ((lane & 3) == 0) {
        size_t lidx = (((size_t)quarter * BB + b) * NHD + h) * LQ;
        g_lP[lidx + qr] = l0;
        g_lP[lidx + qr + 8] = l1;
    }
}

// ---------------- split-K merge (reads partials ONCE) ----------------
__global__ void attn_merge_kernel(__nv_bfloat16* __restrict__ attout) {
    int p = blockIdx.x * blockDim.x + threadIdx.x;
    const int PPR = CC / 2;
    int row = p / PPR, c2 = (p % PPR) * 2;
    int b = row / LQ, q = row % LQ;
    int h = c2 >> 5;
    float l = 0.f;
    #pragma unroll
    for (int s = 0; s < SPLITK; s++)
        l += g_lP[(((size_t)s * BB + b) * NHD + h) * LQ + q];
    float inv = 1.f / l;
    size_t oi = (size_t)row * CC + c2;
    float ox = 0.f, oy = 0.f;
    #pragma unroll
    for (int s = 0; s < SPLITK; s++) {
        float2 a = *(float2*)&g_attP[(size_t)s * BB * LQ * CC + oi];
        ox += a.x; oy += a.y;
    }
    ((unsigned*)attout)[p] = packbf(ox * inv, oy * inv);
}

// ---------------- launch (multi-branch graph) ----------------
extern "C" void kernel_launch(void* const* d_in, const int* in_sizes, int n_in,
                              void* d_out, int out_size) {
    const float* S_QP   = (const float*)d_in[0];
    const float* S_SM   = (const float*)d_in[1];
    const float* f_q    = (const float*)d_in[2];
    const float* P      = (const float*)d_in[3];
    const float* qp_W1  = (const float*)d_in[4];
    const float* qp_b1  = (const float*)d_in[5];
    const float* qp_W2  = (const float*)d_in[6];
    const float* qp_b2  = (const float*)d_in[7];
    const float* phiQ_W1 = (const float*)d_in[8];
    const float* phiQ_b1 = (const float*)d_in[9];
    const float* phiQ_W2 = (const float*)d_in[10];
    const float* phiQ_b2 = (const float*)d_in[11];
    const float* Wq = (const float*)d_in[12];
    const float* bq = (const float*)d_in[13];
    const float* Wk = (const float*)d_in[14];
    const float* bk = (const float*)d_in[15];
    const float* Wv = (const float*)d_in[16];
    const float* bv = (const float*)d_in[17];
    const float* Wo = (const float*)d_in[18];
    const float* bo = (const float*)d_in[19];
    const float* phi_W = (const float*)d_in[20];
    const float* phi_b = (const float*)d_in[21];
    float* out = (float*)d_out;

    float *p_sproj, *p_pp, *p_Wcomb, *p_bcomb;
    __nv_bfloat16 *p_hqb, *p_Qb, *p_fqT, *p_qb, *p_kb, *p_vT, *p_attb;
    cudaGetSymbolAddress((void**)&p_sproj, g_sproj);
    cudaGetSymbolAddress((void**)&p_pp, g_pp);
    cudaGetSymbolAddress((void**)&p_Wcomb, g_Wcomb);
    cudaGetSymbolAddress((void**)&p_bcomb, g_bcomb);
    cudaGetSymbolAddress((void**)&p_hqb, g_hqb);
    cudaGetSymbolAddress((void**)&p_Qb, g_Qb);
    cudaGetSymbolAddress((void**)&p_fqT, g_fqT);
    cudaGetSymbolAddress((void**)&p_qb, g_qb);
    cudaGetSymbolAddress((void**)&p_kb, g_kb);
    cudaGetSymbolAddress((void**)&p_vT, g_vT);
    cudaGetSymbolAddress((void**)&p_attb, g_attb);

    // 1/sqrt(32) * log2(e): logits emitted directly in log2 domain
    const float attnScale = 0.17677669529663687f * LOG2E;

    static cudaStream_t s1 = nullptr, s2 = nullptr, s3 = nullptr;
    static cudaEvent_t evRoot = nullptr, ev1 = nullptr, ev2 = nullptr, ev3 = nullptr;
    if (!s1) {
        cudaStreamCreateWithFlags(&s1, cudaStreamNonBlocking);
        cudaStreamCreateWithFlags(&s2, cudaStreamNonBlocking);
        cudaStreamCreateWithFlags(&s3, cudaStreamNonBlocking);
        cudaEventCreateWithFlags(&evRoot, cudaEventDisableTiming);
        cudaEventCreateWithFlags(&ev1, cudaEventDisableTiming);
        cudaEventCreateWithFlags(&ev2, cudaEventDisableTiming);
        cudaEventCreateWithFlags(&ev3, cudaEventDisableTiming);
    }

    cudaEventRecord(evRoot, 0);
    cudaStreamWaitEvent(s1, evRoot, 0);
    cudaStreamWaitEvent(s2, evRoot, 0);
    cudaStreamWaitEvent(s3, evRoot, 0);

    // ---- branch A (main): mean -> sproj(wide) -> tf32 hproj -> P_hat/V ----
    mean_partial_kernel<<<dim3(16, BB), 256>>>(S_SM);
    meansproj_kernel<<<dim3(BB, 8), 256>>>(qp_W1, qp_b1);
    gemm_tf32_hproj_kernel<<<dim3(64, 4, BB), 128>>>(
        f_q, (long)CC * LK, qp_W1 + (size_t)CC * CC, p_sproj, qp_W2, p_pp, LK);
    phat_final_kernel<<<(BB * LK) / 256, 256>>>(P, qp_b2, out);

    // ---- branch B (s1): transpose -> fused k/v ----
    transpose_fq_kernel<<<dim3(LK / 32, CC / 32, BB), 256, 0, s1>>>(f_q);
    hgemm_kv_kernel<<<dim3(64, 4, BB), 128, 0, s1>>>(
        p_fqT, (long)LK * CC, Wk, Wv, bk, bv,
        p_kb, (long)LK * CC, p_vT, (long)CC * LK, 4096, 256, 256);

    // ---- branch C (s2): hq -> Q -> q ----
    hgemm_cat_kernel<<<dim3(32, 4, 1), 128, 0, s2>>>(
        S_QP, S_SM, phiQ_W1, phiQ_b1, p_hqb, 2048, 256, 512);
    hgemm_kernel<0, 1><<<dim3(32, 4, 1), 128, 0, s2>>>(
        p_hqb, 0, phiQ_W2, CC, phiQ_b2, 0, nullptr,
        nullptr, p_Qb, 0, 1.f, 2048, 256, 256);
    hgemm_kernel<0, 1><<<dim3(32, 4, 1), 128, 0, s2>>>(
        p_Qb, 0, Wq, CC, bq, 0, nullptr,
        nullptr, p_qb, 0, attnScale, 2048, 256, 256);

    // ---- branch D (s3): Wcomb = Wo@phi_W ; bcomb (hidden under prologue+attention) ----
    wcomb_gemm_kernel<<<dim3(4, 4), 256, 0, s3>>>(Wo, phi_W);
    bcomb_kernel<<<1, 256, 0, s3>>>(phi_W, bo, phi_b);

    // join compute branches for attention
    cudaEventRecord(ev1, s1);
    cudaEventRecord(ev2, s2);
    cudaStreamWaitEvent(0, ev1, 0);
    cudaStreamWaitEvent(0, ev2, 0);

    // ---- tail: attention -> merge (reads partials once) -> single fused GEMM ----
    attn_mma_kernel<<<dim3(LQ / 64, NHD, BB * SPLITK), 128>>>(p_qb, p_kb, p_vT);
    attn_merge_kernel<<<(BB * LQ * CC / 2) / 256, 256>>>(p_attb);
    cudaEventRecord(ev3, s3);
    cudaStreamWaitEvent(0, ev3, 0);
    // out = S_SM - (attb @ Wcomb + bcomb)
    hgemm_kernel<2, 0><<<dim3(32, 4, 1), 128>>>(
        p_attb, 0, p_Wcomb, CC, p_bcomb, 0, S_SM,
        out, nullptr, 0, 1.f, 2048, 256, 256);
}